// round 14
// baseline (speedup 1.0000x reference)
#include <cuda_runtime.h>
#include <cuda_bf16.h>
#include <mma.h>
#include <math.h>

using namespace nvcuda;

// ---------------------------------------------------------------------------
// Problem constants: B=32, S=T=64, E=H=512, G=3H=1536, V=32000
// ---------------------------------------------------------------------------

#define OF_ESRCB 0ul          /* bf16 2048x512  (524288 f) */
#define OF_ETGTB 524288ul     /* bf16 2048x512  */
#define OF_GXF   1048576ul    /* f32 2048x1536  */
#define OF_GXB   4194304ul
#define OF_DGX   7340032ul
#define OF_SRCHB 10485760ul   /* bf16 2048x1024 (1048576 f) */
#define OF_UH    11534336ul   /* f32 2048x512   */
#define OF_DOUT  12582912ul   /* f32 2048x512   */
#define OF_DOB   13631488ul   /* bf16 2048x512  */
#define OF_HF    14155776ul   /* 2*32*512 double buffer */
#define OF_HB    14188544ul
#define OF_HD    14221312ul
#define OF_AL    14270464ul   /* 32*64  */
#define OF_LP    14272512ul   /* 2048*256 (125 pairs/row, stride 256) */
#define OF_CON   15296512ul
#define OF_CNT   15298560ul
#define OF_PB    15300608ul   /* bf16 PT: [32][1536][64] (1572864 f) */
#define OF_WF16  16873472ul   /* bf16 1536x512  */
#define OF_WB16  17266688ul
#define OF_WD16  17659904ul   /* bf16 1536x1536 */
#define OF_UW16  18839552ul   /* bf16 512x1024  */
#define OF_OW16  19101696ul   /* bf16 32000x512 */
#define OF_AWB   27293696ul   /* bf16 512x512 A_W (131072 f) */
#define BUF_TOTAL 27424768ul

__device__ __align__(16) float g_buf[BUF_TOTAL];

// fast grid-barrier state (reset every replay by k_init)
__device__ volatile unsigned g_slot[2][128];
// logits row compaction + zero-row logZ
__device__ int g_rows[2048];
__device__ int g_nrows;
__device__ float g_M0, g_L0;

__device__ __forceinline__ float sigm(float x) { return 1.f / (1.f + __expf(-x)); }
__device__ __forceinline__ float dot4(float4 a, float4 b, float acc) {
    acc = fmaf(a.x, b.x, acc); acc = fmaf(a.y, b.y, acc);
    acc = fmaf(a.z, b.z, acc); acc = fmaf(a.w, b.w, acc);
    return acc;
}
__device__ __forceinline__ float blo(unsigned u) { return __uint_as_float(u << 16); }
__device__ __forceinline__ float bhi(unsigned u) { return __uint_as_float(u & 0xffff0000u); }

__device__ __forceinline__ unsigned smem_u32(const void* p) {
    unsigned a;
    asm("{ .reg .u64 t; cvta.to.shared.u64 t, %1; cvt.u32.u64 %0, t; }"
        : "=r"(a) : "l"(p));
    return a;
}

// cp.async helpers (sm_80+)
#define CP16(dst, src) \
    asm volatile("cp.async.cg.shared.global [%0], [%1], 16;" \
                 :: "r"(dst), "l"(src) : "memory")
#define CP_COMMIT() asm volatile("cp.async.commit_group;" ::: "memory")
#define CP_WAIT(n)  asm volatile("cp.async.wait_group %0;" :: "n"(n) : "memory")

// Fast software grid barrier: per-block slot store + all-blocks warp-0 poll.
// All participating blocks co-resident.
__device__ __forceinline__ void gbar(int idx, unsigned e, int nb, int bid) {
    __syncthreads();
    if (threadIdx.x == 0) { __threadfence(); g_slot[idx][bid] = e + 1u; }
    if (threadIdx.x < 32) {
        unsigned v;
        do {
            v = 0xffffffffu;
            for (int s = threadIdx.x; s < nb; s += 32) {
                unsigned sv = g_slot[idx][s];
                v = sv < v ? sv : v;
            }
        } while (!__all_sync(0xffffffffu, v > e));
        __threadfence();
    }
    __syncthreads();
}

// ---------------------------------------------------------------------------
// k_init: zero hidden states + barrier state; row compaction; logz0
// grid 66 x 256
// ---------------------------------------------------------------------------
__global__ void k_init(const int* __restrict__ tlen, const float* __restrict__ ob) {
    int bid = blockIdx.x, t = threadIdx.x;
    if (bid < 64) {
        int i = bid * 256 + t;
        g_buf[OF_HF + i] = 0.f;
        g_buf[OF_HB + i] = 0.f;
        g_buf[OF_HD + i] = 0.f;
        if (bid == 0 && t < 128) { g_slot[0][t] = 0u; g_slot[1][t] = 0u; }
    } else if (bid == 64) {
        __shared__ int offs[32];
        if (t == 0) {
            int a = 0;
            for (int b = 0; b < 32; b++) { offs[b] = a; a += tlen[b]; }
            g_nrows = a;
        }
        __syncthreads();
        for (int i = t; i < 2048; i += 256) g_rows[i] = 2047;
        __syncthreads();
        for (int b = 0; b < 32; b++) {
            int L = tlen[b];
            for (int tc = t; tc < L; tc += 256)
                g_rows[offs[b] + tc] = b * 64 + tc;
        }
    } else {
        __shared__ float red[8];
        int lane = t & 31, w = t >> 5;
        float m = -1e30f;
        for (int i = t; i < 32000; i += 256) m = fmaxf(m, ob[i]);
#pragma unroll
        for (int o = 16; o > 0; o >>= 1)
            m = fmaxf(m, __shfl_xor_sync(0xffffffffu, m, o));
        if (lane == 0) red[w] = m;
        __syncthreads();
        if (t == 0) {
            float v = red[0];
            for (int i = 1; i < 8; i++) v = fmaxf(v, red[i]);
            red[0] = v;
        }
        __syncthreads();
        float M = red[0];
        __syncthreads();
        float l = 0.f;
        for (int i = t; i < 32000; i += 256) l += __expf(ob[i] - M);
#pragma unroll
        for (int o = 16; o > 0; o >>= 1) l += __shfl_xor_sync(0xffffffffu, l, o);
        if (lane == 0) red[w] = l;
        __syncthreads();
        if (t == 0) {
            float s = 0.f;
            for (int i = 0; i < 8; i++) s += red[i];
            g_M0 = M; g_L0 = s;
        }
    }
}

// ---------------------------------------------------------------------------
// k_prep: all fp32->bf16 weight conversions + both embedding gathers
// grid 12352 x 256
// ---------------------------------------------------------------------------
__device__ __forceinline__ uint4 cvt8(float4 a, float4 b) {
    __nv_bfloat162 h0 = __floats2bfloat162_rn(a.x, a.y);
    __nv_bfloat162 h1 = __floats2bfloat162_rn(a.z, a.w);
    __nv_bfloat162 h2 = __floats2bfloat162_rn(b.x, b.y);
    __nv_bfloat162 h3 = __floats2bfloat162_rn(b.z, b.w);
    uint4 u;
    u.x = *(unsigned*)&h0; u.y = *(unsigned*)&h1;
    u.z = *(unsigned*)&h2; u.w = *(unsigned*)&h3;
    return u;
}
__global__ void k_prep(
    const float* __restrict__ eWih_f, const float* __restrict__ eWih_b,
    const float* __restrict__ dWih, const float* __restrict__ U_w,
    const float* __restrict__ out_w, const float* __restrict__ A_W,
    const int* __restrict__ src_seqs, const float* __restrict__ src_emb,
    const int* __restrict__ tgt_seqs, const float* __restrict__ tgt_emb)
{
    int bid = blockIdx.x, t = threadIdx.x;
    if (bid < 10304) {
        const float* src; size_t dst; int base;
        if (bid < 384)        { src = eWih_f; dst = OF_WF16; base = 0; }
        else if (bid < 768)   { src = eWih_b; dst = OF_WB16; base = 384; }
        else if (bid < 1920)  { src = dWih;   dst = OF_WD16; base = 768; }
        else if (bid < 2176)  { src = U_w;    dst = OF_UW16; base = 1920; }
        else if (bid < 10176) { src = out_w;  dst = OF_OW16; base = 2176; }
        else                  { src = A_W;    dst = OF_AWB;  base = 10176; }
        size_t i = (size_t)(bid - base) * 256 + t;
        float4 a = ((const float4*)src)[i*2];
        float4 b = ((const float4*)src)[i*2 + 1];
        ((uint4*)(g_buf + dst))[i] = cvt8(a, b);
    } else {
        int eb = bid - 10304;
        const int* ids; const float* tab; size_t dst;
        if (eb < 1024) { ids = src_seqs; tab = src_emb; dst = OF_ESRCB; }
        else { eb -= 1024; ids = tgt_seqs; tab = tgt_emb; dst = OF_ETGTB; }
        int row = eb * 2 + (t >> 7), lane = t & 127;
        float4 v = ((const float4*)(tab + (size_t)ids[row] * 512))[lane];
        __nv_bfloat162 h0 = __floats2bfloat162_rn(v.x, v.y);
        __nv_bfloat162 h1 = __floats2bfloat162_rn(v.z, v.w);
        uint2 u; u.x = *(unsigned*)&h0; u.y = *(unsigned*)&h1;
        ((uint2*)(g_buf + dst))[(size_t)row * 128 + lane] = u;
    }
}

// ---------------------------------------------------------------------------
// bf16 GEMM core: BM=128 x BN=256 x BK=32, 256 thr (8 warps, 2x4, 64x64/warp).
// cp.async double-buffered smem (stride 40 halves). C = A @ W^T.
// mode: 0 = fp32 store (+bias); 1 = bf16 P-transposed store; 2 = fused
// (max,sumexp) logsumexp partials. dyn smem = 61440 B.
// ---------------------------------------------------------------------------
__device__ __forceinline__ void mm256_body(
    __nv_bfloat16* smh, const __nv_bfloat16* A, int lda,
    const __nv_bfloat16* W, int ldw, const float* bias,
    size_t c_off, int ldc, int K, int mode,
    int bm, int bn, const int* rid, const float* bsh)
{
    int t = threadIdx.x, wid = t >> 5;
    int wm = (wid >> 2) * 64, wn4 = wid & 3;
    unsigned sb = smem_u32(smh);

    wmma::fragment<wmma::accumulator, 16, 16, 16, float> acc[4][4];
#pragma unroll
    for (int i = 0; i < 4; i++)
#pragma unroll
        for (int j = 0; j < 4; j++) wmma::fill_fragment(acc[i][j], 0.f);

    int ar = t >> 1, as2 = (t & 1) * 2;
    const int arow = rid[ar];

#define MM_ISSUE(c) {                                                           \
        int kb = (c) * 32;                                                      \
        unsigned ab = sb + (unsigned)((c) & 1) * 30720u;                        \
        const __nv_bfloat16* sa = A + (size_t)arow * lda + kb + as2 * 8;        \
        unsigned da = ab + (unsigned)ar * 80u + (unsigned)as2 * 16u;            \
        CP16(da, sa); CP16(da + 16u, sa + 8);                                   \
        const __nv_bfloat16* sw = W + (size_t)(bn + t) * ldw + kb;              \
        unsigned db = ab + 10240u + (unsigned)t * 80u;                          \
        CP16(db, sw); CP16(db + 16u, sw + 8);                                   \
        CP16(db + 32u, sw + 16); CP16(db + 48u, sw + 24);                       \
        CP_COMMIT(); }

    MM_ISSUE(0)
    int nk = K / 32;
    for (int c = 0; c < nk; c++) {
        if (c + 1 < nk) { MM_ISSUE(c + 1) CP_WAIT(1); }
        else CP_WAIT(0);
        __syncthreads();
        const __nv_bfloat16* As = smh + (size_t)(c & 1) * 15360;
        const __nv_bfloat16* Bs = As + 5120;
#pragma unroll
        for (int kk = 0; kk < 32; kk += 16) {
            wmma::fragment<wmma::matrix_a, 16, 16, 16, __nv_bfloat16,
                           wmma::row_major> af[4];
            wmma::fragment<wmma::matrix_b, 16, 16, 16, __nv_bfloat16,
                           wmma::col_major> bf[4];
#pragma unroll
            for (int i = 0; i < 4; i++)
                wmma::load_matrix_sync(af[i], As + (wm + i*16) * 40 + kk, 40);
#pragma unroll
            for (int j = 0; j < 4; j++)
                wmma::load_matrix_sync(bf[j], Bs + (wn4*64 + j*16) * 40 + kk, 40);
#pragma unroll
            for (int i = 0; i < 4; i++)
#pragma unroll
                for (int j = 0; j < 4; j++)
                    wmma::mma_sync(acc[i][j], af[i], bf[j], acc[i][j]);
        }
        __syncthreads();
    }
#undef MM_ISSUE

    float* Cs = (float*)smh;
    int r = t >> 1, half = t & 1;
    float M = -1e30f, L = 0.f;
#pragma unroll
    for (int p = 0; p < 4; p++) {
        __syncthreads();
#pragma unroll
        for (int i = 0; i < 4; i++)
            wmma::store_matrix_sync(Cs + (size_t)(wm + i*16) * 68 + wn4 * 16,
                                    acc[i][p], 68, wmma::mem_row_major);
        __syncthreads();
        if (mode == 2) {
            float m = -1e30f, v[32];
#pragma unroll
            for (int pi = 0; pi < 2; pi++) {
                int cc = half * 32 + pi * 16;
                int gc = (cc >> 4) * 64 + p * 16;
#pragma unroll
                for (int u = 0; u < 16; u++) {
                    float x = Cs[(size_t)r * 68 + cc + u] + bsh[gc + u];
                    v[pi*16 + u] = x; m = fmaxf(m, x);
                }
            }
            float l = 0.f;
#pragma unroll
            for (int u = 0; u < 32; u++) l += __expf(v[u] - m);
            float nM = fmaxf(M, m);
            L = L * __expf(M - nM) + l * __expf(m - nM);
            M = nM;
        } else if (mode == 1) {
            int b_ = (bm + r) >> 6, s_ = (bm + r) & 63;
            __nv_bfloat16* Pt = ((__nv_bfloat16*)g_buf) + 2*OF_PB;
#pragma unroll
            for (int pi = 0; pi < 2; pi++) {
                int cc = half * 32 + pi * 16;
                int g0 = bn + (cc >> 4) * 64 + p * 16;
                for (int u = 0; u < 16; u++)
                    Pt[(size_t)b_ * 98304 + (size_t)(g0 + u) * 64 + s_] =
                        __float2bfloat16(Cs[(size_t)r * 68 + cc + u]);
            }
        } else {
#pragma unroll
            for (int pi = 0; pi < 2; pi++) {
                int cc = half * 32 + pi * 16;
                int g0 = bn + (cc >> 4) * 64 + p * 16;
                float* Crow = g_buf + c_off + (size_t)(bm + r) * ldc + g0;
#pragma unroll
                for (int u = 0; u < 16; u += 4) {
                    float4 x = *(float4*)(Cs + (size_t)r * 68 + cc + u);
                    if (bias) {
                        float4 bv = *(const float4*)(bias + g0 + u);
                        x.x += bv.x; x.y += bv.y; x.z += bv.z; x.w += bv.w;
                    }
                    *(float4*)(Crow + u) = x;
                }
            }
        }
    }
    if (mode == 2) {
        float M2 = __shfl_xor_sync(0xffffffffu, M, 1);
        float L2 = __shfl_xor_sync(0xffffffffu, L, 1);
        float nM = fmaxf(M, M2);
        float LL = L * __expf(M - nM) + L2 * __expf(M2 - nM);
        if (half == 0) {
            size_t orow = (size_t)rid[r];
            g_buf[OF_LP + orow * 256 + (size_t)blockIdx.x * 2]     = nM;
            g_buf[OF_LP + orow * 256 + (size_t)blockIdx.x * 2 + 1] = LL;
        }
    }
}

// Generic wrapper: logits (mode2 + row gather)
__global__ __launch_bounds__(256) void k_mm256(
    size_t a_hoff, int lda, size_t w_hoff, int ldw,
    const float* __restrict__ bias, size_t c_off, int ldc, int K,
    int mode, int use_rows)
{
    extern __shared__ __nv_bfloat16 smh[];
    __shared__ int rid[128];
    __shared__ float bsh[256];
    int bm = blockIdx.y * 128, bn = blockIdx.x * 256;
    if (mode == 2 && bm >= g_nrows) return;
    int t = threadIdx.x;
    if (t < 128) rid[t] = use_rows ? g_rows[bm + t] : (bm + t);
    if (mode == 2) bsh[t] = bias[bn + t];
    __syncthreads();
    mm256_body(smh, ((const __nv_bfloat16*)g_buf) + a_hoff, lda,
               ((const __nv_bfloat16*)g_buf) + w_hoff, ldw, bias,
               c_off, ldc, K, mode, bm, bn, rid, bsh);
}

// Fused Uh (x<2, mode0) + P (x>=2, mode1): grid (8, 16)
__global__ __launch_bounds__(256) void k_uhp(const float* __restrict__ U_b)
{
    extern __shared__ __nv_bfloat16 smh[];
    __shared__ int rid[128];
    int bm = blockIdx.y * 128;
    int t = threadIdx.x;
    if (t < 128) rid[t] = bm + t;
    __syncthreads();
    if (blockIdx.x < 2) {
        int bn = blockIdx.x * 256;
        mm256_body(smh, ((const __nv_bfloat16*)g_buf) + 2*OF_SRCHB, 1024,
                   ((const __nv_bfloat16*)g_buf) + 2*OF_UW16, 1024, U_b,
                   OF_UH, 512, 1024, 0, bm, bn, rid, (const float*)0);
    } else {
        int bn = (blockIdx.x - 2) * 256;
        mm256_body(smh, ((const __nv_bfloat16*)g_buf) + 2*OF_SRCHB, 1024,
                   ((const __nv_bfloat16*)g_buf) + 2*OF_WD16 + 512, 1536,
                   (const float*)0, OF_PB, 0, 1024, 1, bm, bn, rid,
                   (const float*)0);
    }
}

// Fused gate pre-GEMMs: seg 0=GXF 1=GXB 2=DGX. grid (18, 16)
__global__ __launch_bounds__(256) void k_gates256(
    const float* __restrict__ bf, const float* __restrict__ bb,
    const float* __restrict__ bd)
{
    extern __shared__ __nv_bfloat16 smh[];
    __shared__ int rid[128];
    int seg = blockIdx.x / 6, xb = blockIdx.x % 6;
    size_t a_hoff = (seg == 2) ? 2*OF_ETGTB : 2*OF_ESRCB;
    size_t w_hoff = (seg == 0) ? 2*OF_WF16 : (seg == 1) ? 2*OF_WB16 : 2*OF_WD16;
    int ldw = (seg == 2) ? 1536 : 512;
    const float* bias = (seg == 0) ? bf : (seg == 1) ? bb : bd;
    size_t c_off = (seg == 0) ? OF_GXF : (seg == 1) ? OF_GXB : OF_DGX;
    int bm = blockIdx.y * 128, bn = xb * 256;
    int t = threadIdx.x;
    if (t < 128) rid[t] = bm + t;
    __syncthreads();
    mm256_body(smh, ((const __nv_bfloat16*)g_buf) + a_hoff, 512,
               ((const __nv_bfloat16*)g_buf) + w_hoff, ldw, bias,
               c_off, 1536, 512, 0, bm, bn, rid, (const float*)0);
}

// ---------------------------------------------------------------------------
// High-ILP gate GEMM inner: thread (rp, j) computes 3 dots of length 512
// against smem-resident weights (wsh, stride 516) and smem-resident h
// (Hsd, stride 516). 12 split accumulator chains, 16 loads in flight/seg.
// ---------------------------------------------------------------------------
__device__ __forceinline__ void gate_dots(
    const float* __restrict__ wr_, const float* __restrict__ wz_,
    const float* __restrict__ wn_, const float* __restrict__ hr_,
    float& arO, float& azO, float& anO)
{
    float ar0=0.f, ar1=0.f, az0=0.f, az1=0.f, an0=0.f, an1=0.f;
#pragma unroll 2
    for (int kq = 0; kq < 32; kq++) {
        int kb = kq * 16;
        float4 h0 = *(const float4*)(hr_ + kb);
        float4 h1 = *(const float4*)(hr_ + kb + 4);
        float4 h2 = *(const float4*)(hr_ + kb + 8);
        float4 h3 = *(const float4*)(hr_ + kb + 12);
        float4 r0 = *(const float4*)(wr_ + kb);
        float4 r1 = *(const float4*)(wr_ + kb + 4);
        float4 r2 = *(const float4*)(wr_ + kb + 8);
        float4 r3 = *(const float4*)(wr_ + kb + 12);
        float4 z0 = *(const float4*)(wz_ + kb);
        float4 z1 = *(const float4*)(wz_ + kb + 4);
        float4 z2 = *(const float4*)(wz_ + kb + 8);
        float4 z3 = *(const float4*)(wz_ + kb + 12);
        float4 n0 = *(const float4*)(wn_ + kb);
        float4 n1 = *(const float4*)(wn_ + kb + 4);
        float4 n2 = *(const float4*)(wn_ + kb + 8);
        float4 n3 = *(const float4*)(wn_ + kb + 12);
        ar0 = dot4(h0, r0, ar0); ar1 = dot4(h1, r1, ar1);
        az0 = dot4(h0, z0, az0); az1 = dot4(h1, z1, az1);
        an0 = dot4(h0, n0, an0); an1 = dot4(h1, n1, an1);
        ar0 = dot4(h2, r2, ar0); ar1 = dot4(h3, r3, ar1);
        az0 = dot4(h2, z2, az0); az1 = dot4(h3, z3, az1);
        an0 = dot4(h2, n2, an0); an1 = dot4(h3, n3, an1);
    }
    arO = ar0 + ar1; azO = az0 + az1; anO = an0 + an1;
}

// ---------------------------------------------------------------------------
// Persistent encoder: 128 blocks x 256 thr, 64 steps, barrier idx 0
// (epochs 0..62). Whh slice (24x512) + full h (32x512) smem-resident.
// dyn smem = 56*516*4 = 115584 B.
// ---------------------------------------------------------------------------
__global__ __launch_bounds__(256) void k_enc_all(
    const float* __restrict__ Whh_f, const float* __restrict__ bhh_f,
    const float* __restrict__ Whh_b, const float* __restrict__ bhh_b,
    const int* __restrict__ slen)
{
    extern __shared__ float dsm[];
    float* wsh = dsm;               // [24][516]
    float* Hsd = dsm + 24 * 516;    // [32][516]
    int bid = blockIdx.x;
    int dir = bid >> 6;
    int j0 = (bid & 63) * 8;
    const float* Whh = dir ? Whh_b : Whh_f;
    const float* bhh = dir ? bhh_b : bhh_f;
    size_t hb = dir ? OF_HB : OF_HF;
    const float* gx = g_buf + (dir ? OF_GXB : OF_GXF);
    __nv_bfloat16* srch = ((__nv_bfloat16*)g_buf) + 2*OF_SRCHB;
    int t = threadIdx.x;

    for (int i = t; i < 24 * 128; i += 256) {
        int wr = i >> 7, c4 = (i & 127) * 4;
        int gw = (wr >> 3) * 512 + j0 + (wr & 7);
        *(float4*)&wsh[wr * 516 + c4] = *(const float4*)(Whh + (size_t)gw * 512 + c4);
    }

    int rp = t >> 3, j = t & 7, jg = j0 + j;
    float br = bhh[jg], bz = bhh[512 + jg], bnn = bhh[1024 + jg];
    int sl = slen[rp];
    const float* wr_ = wsh + (size_t)j * 516;
    const float* wz_ = wsh + (size_t)(8 + j) * 516;
    const float* wn_ = wsh + (size_t)(16 + j) * 516;
    const float* hr_ = Hsd + (size_t)rp * 516;

    for (int s = 0; s < 64; s++) {
        if (s > 0) gbar(0, (unsigned)(s - 1), 128, bid);
        else __syncthreads();
        int pin = s & 1;
        const float* hin = g_buf + hb + (size_t)pin * 16384;
        float* hout = g_buf + hb + (size_t)(pin ^ 1) * 16384;
        int tt = dir ? (63 - s) : s;

        // stage full h (32x512) in smem once
#pragma unroll
        for (int i = 0; i < 2; i++) {
            int vec = t + 256 * i;       // 0..511 float4s
            int rr = vec >> 4, kv = vec & 15;
            *(float4*)&Hsd[rr * 516 + kv * 4] =
                *(const float4*)(hin + (size_t)rr * 512 + kv * 4);
        }
        __syncthreads();

        float ar, az, an;
        gate_dots(wr_, wz_, wn_, hr_, ar, az, an);

        size_t grow = (size_t)rp * 64 + tt;
        float gxr = gx[grow*1536 + jg];
        float gxz = gx[grow*1536 + 512 + jg];
        float gxn = gx[grow*1536 + 1024 + jg];
        float rr = sigm(gxr + ar + br);
        float zz = sigm(gxz + az + bz);
        float nn = tanhf(gxn + rr * (an + bnn));
        float hold = hin[(size_t)rp*512 + jg];
        float hnew = (1.f - zz) * nn + zz * hold;
        bool m = tt < sl;
        hout[(size_t)rp*512 + jg] = m ? hnew : hold;
        srch[grow*1024 + (size_t)dir*512 + jg] = __float2bfloat16(m ? hnew : 0.f);
    }
}

// ---------------------------------------------------------------------------
// Persistent decoder: 96 blocks x 256 thr, 64 steps, 2 barriers/step.
//   blocks  0-31 : A — Uh[b] smem-resident; q from bf16 A_W (L2);
//                      scores/softmax; publish alpha
//   blocks 32-95 : G — gate dots vs smem Whh + smem h; ctx from bf16 P^T; GRU
// barriers: idx0 = h ready (epochs 64+), idx1 = alpha ready (epochs 0..63)
// dyn smem = 131072 B (A: Uh 64x512 f32; G: weights 24x516 + h 32x516)
// ---------------------------------------------------------------------------
__global__ __launch_bounds__(256) void k_dec_all(
    const float* __restrict__ A_b, const float* __restrict__ A_v,
    const float* __restrict__ Whh, const float* __restrict__ bhh,
    const int* __restrict__ slen, const int* __restrict__ tlen)
{
    extern __shared__ float dsm[];
    __shared__ float es[64];
    __shared__ float hs[512];
    __shared__ float qsh[512];
    __shared__ float als[32][64];

    int bid = blockIdx.x;
    int t = threadIdx.x;
    int lane = t & 31;
    bool isA = bid < 32;
    int b  = bid;
    int j0 = (bid - 32) * 8;
    float* wsh = dsm;               // G: [24][516]
    float* Hsd = dsm + 24 * 516;    // G: [32][516]

    const __nv_bfloat16* AWb = ((const __nv_bfloat16*)g_buf) + 2*OF_AWB;
    float avr[16], ab0 = 0.f, ab1 = 0.f;
    if (isA) {
        for (int i = t; i < 8192; i += 256)
            *(float4*)&dsm[(size_t)i*4] =
                *(const float4*)(g_buf + OF_UH + (size_t)b*32768 + (size_t)i*4);
#pragma unroll
        for (int k = 0; k < 16; k++) avr[k] = A_v[lane + 32*k];
        ab0 = A_b[t]; ab1 = A_b[t + 256];
    } else {
        for (int i = t; i < 24 * 128; i += 256) {
            int wr = i >> 7, c4 = (i & 127) * 4;
            int gw = (wr >> 3) * 512 + j0 + (wr & 7);
            *(float4*)&wsh[wr * 516 + c4] =
                *(const float4*)(Whh + (size_t)gw * 512 + c4);
        }
    }

    int rp = t >> 3, j = t & 7, jg = j0 + j;
    float br = 0.f, bz = 0.f, bnn = 0.f;
    int tl = 64;
    if (!isA) {
        br = bhh[jg]; bz = bhh[512 + jg]; bnn = bhh[1024 + jg];
        tl = tlen[rp];
    }
    int sl = isA ? slen[b] : 0;
    const __nv_bfloat16* Pt = ((const __nv_bfloat16*)g_buf) + 2*OF_PB;
    __nv_bfloat16* dob = ((__nv_bfloat16*)g_buf) + 2*OF_DOB;
    const float* wr_ = wsh + (size_t)j * 516;
    const float* wz_ = wsh + (size_t)(8 + j) * 516;
    const float* wn_ = wsh + (size_t)(16 + j) * 516;
    const float* hr_ = Hsd + (size_t)rp * 516;

    for (int step = 0; step < 64; step++) {
        if (step > 0) gbar(0, (unsigned)(63 + step), 96, bid);   // h published
        else __syncthreads();
        int pin = step & 1;
        const float* hin = g_buf + OF_HD + (size_t)pin * 16384;
        float* hout = g_buf + OF_HD + (size_t)(pin ^ 1) * 16384;

        float ar = 0.f, az = 0.f, an = 0.f;
        if (isA) {
            hs[t]       = hin[(size_t)b*512 + t];
            hs[t + 256] = hin[(size_t)b*512 + t + 256];
            __syncthreads();
            // q: cols t and t+256, bf16 A_W from L2
            float a0 = ab0, a1 = ab1;
            const uint4* w0 = (const uint4*)(AWb + (size_t)t * 512);
            const uint4* w1 = (const uint4*)(AWb + (size_t)(t + 256) * 512);
#pragma unroll 8
            for (int q = 0; q < 64; q++) {
                uint4 u0 = w0[q], u1 = w1[q];
                float4 h0 = *(const float4*)&hs[q*8];
                float4 h1 = *(const float4*)&hs[q*8 + 4];
                a0 = fmaf(blo(u0.x), h0.x, a0); a0 = fmaf(bhi(u0.x), h0.y, a0);
                a0 = fmaf(blo(u0.y), h0.z, a0); a0 = fmaf(bhi(u0.y), h0.w, a0);
                a0 = fmaf(blo(u0.z), h1.x, a0); a0 = fmaf(bhi(u0.z), h1.y, a0);
                a0 = fmaf(blo(u0.w), h1.z, a0); a0 = fmaf(bhi(u0.w), h1.w, a0);
                a1 = fmaf(blo(u1.x), h0.x, a1); a1 = fmaf(bhi(u1.x), h0.y, a1);
                a1 = fmaf(blo(u1.y), h0.z, a1); a1 = fmaf(bhi(u1.y), h0.w, a1);
                a1 = fmaf(blo(u1.z), h1.x, a1); a1 = fmaf(bhi(u1.z), h1.y, a1);
                a1 = fmaf(blo(u1.w), h1.z, a1); a1 = fmaf(bhi(u1.w), h1.w, a1);
            }
            qsh[t] = a0; qsh[t + 256] = a1;
            __syncthreads();
            float qr[16];
#pragma unroll
            for (int k = 0; k < 16; k++) qr[k] = qsh[lane + 32*k];
            int w = t >> 5;
#pragma unroll
            for (int si = 0; si < 8; si++) {
                int s = w*8 + si;
                float acc = 0.f;
#pragma unroll
                for (int k = 0; k < 16; k++) {
                    float x = dsm[(size_t)s*512 + lane + 32*k] + qr[k];
                    float th;
                    asm("tanh.approx.f32 %0, %1;" : "=f"(th) : "f"(x));
                    acc = fmaf(avr[k], th, acc);
                }
#pragma unroll
                for (int o = 16; o > 0; o >>= 1)
                    acc += __shfl_xor_sync(0xffffffffu, acc, o);
                if (lane == 0) es[s] = (s < sl) ? acc : acc - 1e9f;
            }
            __syncthreads();
            if (t < 32) {
                float a0s = es[t], a1s = es[t + 32];
                float m = fmaxf(a0s, a1s);
#pragma unroll
                for (int o = 16; o > 0; o >>= 1)
                    m = fmaxf(m, __shfl_xor_sync(0xffffffffu, m, o));
                float e0 = __expf(a0s - m), e1 = __expf(a1s - m);
                float sum = e0 + e1;
#pragma unroll
                for (int o = 16; o > 0; o >>= 1)
                    sum += __shfl_xor_sync(0xffffffffu, sum, o);
                es[t] = e0 / sum; es[t + 32] = e1 / sum;
            }
            __syncthreads();
            if (t < 64) g_buf[OF_AL + (size_t)b*64 + t] = es[t];
        } else {
            // G: stage full h in smem, then high-ILP gate dots
#pragma unroll
            for (int i = 0; i < 2; i++) {
                int vec = t + 256 * i;
                int rr = vec >> 4, kv = vec & 15;
                *(float4*)&Hsd[rr * 516 + kv * 4] =
                    *(const float4*)(hin + (size_t)rr * 512 + kv * 4);
            }
            __syncthreads();
            gate_dots(wr_, wz_, wn_, hr_, ar, az, an);
        }
        gbar(1, (unsigned)step, 96, bid);                       // alpha ready

        if (!isA) {
            for (int i = t; i < 2048; i += 256)
                als[i >> 6][i & 63] = g_buf[OF_AL + i];
            __syncthreads();
            float cr = 0.f, cz = 0.f, cn = 0.f;
            const uint4* p0 = (const uint4*)(Pt + (size_t)rp*98304 + (size_t)jg*64);
            const uint4* p1 = (const uint4*)(Pt + (size_t)rp*98304 + (size_t)(512 + jg)*64);
            const uint4* p2 = (const uint4*)(Pt + (size_t)rp*98304 + (size_t)(1024 + jg)*64);
#pragma unroll
            for (int q = 0; q < 8; q++) {
                uint4 v0 = p0[q], v1 = p1[q], v2 = p2[q];
                const __nv_bfloat16* h0 = (const __nv_bfloat16*)&v0;
                const __nv_bfloat16* h1 = (const __nv_bfloat16*)&v1;
                const __nv_bfloat16* h2 = (const __nv_bfloat16*)&v2;
#pragma unroll
                for (int u = 0; u < 8; u++) {
                    float al = als[rp][q*8 + u];
                    cr = fmaf(al, __bfloat162float(h0[u]), cr);
                    cz = fmaf(al, __bfloat162float(h1[u]), cz);
                    cn = fmaf(al, __bfloat162float(h2[u]), cn);
                }
            }
            size_t grow = (size_t)rp*64 + step;
            const float* gx = g_buf + OF_DGX + grow*1536;
            float rr = sigm(gx[jg]        + cr + ar + br);
            float zz = sigm(gx[512 + jg]  + cz + az + bz);
            float nn = tanhf(gx[1024 + jg] + cn + rr * (an + bnn));
            float hold = hin[(size_t)rp*512 + jg];
            float hnew = (1.f - zz) * nn + zz * hold;
            bool m = step < tl;
            float o = m ? hnew : 0.f;
            hout[(size_t)rp*512 + jg] = m ? hnew : hold;
            g_buf[OF_DOUT + grow*512 + jg] = o;
            dob[grow*512 + jg] = __float2bfloat16(o);
        }
    }
}

// ---------------------------------------------------------------------------
// Per-row: combine partials (live rows) or shared logZ0 (zero rows)
// ---------------------------------------------------------------------------
__global__ __launch_bounds__(256) void k_combine(
    const int* __restrict__ tgt, const float* __restrict__ out_w,
    const float* __restrict__ out_b, const int* __restrict__ tlen)
{
    int row = blockIdx.x * 8 + (threadIdx.x >> 5);
    int lane = threadIdx.x & 31;
    int b = row >> 6, tc = row & 63;
    int goal = (tc < 63) ? tgt[b*64 + tc + 1] : 0;
    float contrib = 0.f, cnt = 0.f;
    if (goal != 0) {
        bool live = tc < tlen[b];
        float M, L, d = 0.f;
        if (live) {
            const float* p = g_buf + OF_LP + (size_t)row * 256;
            M = -1e30f;
            for (int c = lane; c < 125; c += 32) M = fmaxf(M, p[c*2]);
#pragma unroll
            for (int o = 16; o > 0; o >>= 1)
                M = fmaxf(M, __shfl_xor_sync(0xffffffffu, M, o));
            L = 0.f;
            for (int c = lane; c < 125; c += 32) L += p[c*2+1] * __expf(p[c*2] - M);
#pragma unroll
            for (int o = 16; o > 0; o >>= 1)
                L += __shfl_xor_sync(0xffffffffu, L, o);
            const float* x = g_buf + OF_DOUT + (size_t)row * 512;
            const float* wrow = out_w + (size_t)goal * 512;
            for (int k = lane; k < 512; k += 32) d = fmaf(x[k], wrow[k], d);
#pragma unroll
            for (int o = 16; o > 0; o >>= 1)
                d += __shfl_xor_sync(0xffffffffu, d, o);
        } else {
            M = g_M0; L = g_L0;
        }
        contrib = (d + out_b[goal]) - (M + logf(L));
        cnt = 1.f;
    }
    if (lane == 0) {
        g_buf[OF_CON + row] = contrib;
        g_buf[OF_CNT + row] = cnt;
    }
}

// ---------------------------------------------------------------------------
// Final deterministic reduce -> loss
// ---------------------------------------------------------------------------
__global__ void k_final(float* out) {
    __shared__ float sc[1024], sn[1024];
    int t = threadIdx.x;
    sc[t] = g_buf[OF_CON + t] + g_buf[OF_CON + 1024 + t];
    sn[t] = g_buf[OF_CNT + t] + g_buf[OF_CNT + 1024 + t];
    __syncthreads();
    for (int o = 512; o > 0; o >>= 1) {
        if (t < o) { sc[t] += sc[t+o]; sn[t] += sn[t+o]; }
        __syncthreads();
    }
    if (t == 0) out[0] = -sc[0] / sn[0];
}

// ---------------------------------------------------------------------------
// Host orchestration (graph-capturable: kernel launches only, default stream)
// ---------------------------------------------------------------------------
extern "C" void kernel_launch(void* const* d_in, const int* in_sizes, int n_in,
                              void* d_out, int out_size)
{
    const int*   src_seqs = (const int*)  d_in[0];
    const int*   src_len  = (const int*)  d_in[1];
    const int*   tgt_seqs = (const int*)  d_in[2];
    const int*   tgt_len  = (const int*)  d_in[3];
    const float* src_emb  = (const float*)d_in[4];
    const float* eWih_f   = (const float*)d_in[5];
    const float* eWhh_f   = (const float*)d_in[6];
    const float* ebih_f   = (const float*)d_in[7];
    const float* ebhh_f   = (const float*)d_in[8];
    const float* eWih_b   = (const float*)d_in[9];
    const float* eWhh_b   = (const float*)d_in[10];
    const float* ebih_b   = (const float*)d_in[11];
    const float* ebhh_b   = (const float*)d_in[12];
    const float* tgt_emb  = (const float*)d_in[13];
    const float* dWih     = (const float*)d_in[14];
    const float* dWhh     = (const float*)d_in[15];
    const float* dbih     = (const float*)d_in[16];
    const float* dbhh     = (const float*)d_in[17];
    const float* U_w      = (const float*)d_in[18];
    const float* U_b      = (const float*)d_in[19];
    const float* A_W      = (const float*)d_in[20];
    const float* A_b      = (const float*)d_in[21];
    const float* A_v      = (const float*)d_in[22];
    const float* out_w    = (const float*)d_in[23];
    const float* out_b    = (const float*)d_in[24];

    cudaFuncSetAttribute(k_enc_all,  cudaFuncAttributeMaxDynamicSharedMemorySize, 115584);
    cudaFuncSetAttribute(k_dec_all,  cudaFuncAttributeMaxDynamicSharedMemorySize, 131072);
    cudaFuncSetAttribute(k_mm256,    cudaFuncAttributeMaxDynamicSharedMemorySize, 61440);
    cudaFuncSetAttribute(k_uhp,      cudaFuncAttributeMaxDynamicSharedMemorySize, 61440);
    cudaFuncSetAttribute(k_gates256, cudaFuncAttributeMaxDynamicSharedMemorySize, 61440);

    // 1: init (zero h, barrier state, row compaction, logZ0)
    k_init<<<66, 256>>>(tgt_len, out_b);
    // 2: all weight cvt + embeds in one launch
    k_prep<<<12352, 256>>>(eWih_f, eWih_b, dWih, U_w, out_w, A_W,
                           src_seqs, src_emb, tgt_seqs, tgt_emb);
    // 3: fused gate pre-GEMMs (GXF, GXB, DGX)
    k_gates256<<<dim3(18, 16), 256, 61440>>>(ebih_f, ebih_b, dbih);
    // 4: persistent bidirectional encoder
    k_enc_all<<<128, 256, 115584>>>(eWhh_f, ebhh_f, eWhh_b, ebhh_b, src_len);
    // 5: fused Uh + P
    k_uhp<<<dim3(8, 16), 256, 61440>>>(U_b);
    // 6: persistent decoder (profiled by ncu -s 5 -c 1)
    k_dec_all<<<96, 256, 131072>>>(A_b, A_v, dWhh, dbhh, src_len, tgt_len);
    // 7: logits with fused log-softmax partials
    k_mm256<<<dim3(125, 16), 256, 61440>>>(2*OF_DOB, 512, 2*OF_OW16, 512,
                                           out_b, 0, 0, 512, 2, 1);
    // 8-9: combine + final reduce
    k_combine<<<256, 256>>>(tgt_seqs, out_w, out_b, tgt_len);
    k_final<<<1, 1024>>>((float*)d_out);
}

// round 15
// speedup vs baseline: 1.1677x; 1.1677x over previous
#include <cuda_runtime.h>
#include <cuda_bf16.h>
#include <mma.h>
#include <math.h>

using namespace nvcuda;

// ---------------------------------------------------------------------------
// Problem constants: B=32, S=T=64, E=H=512, G=3H=1536, V=32000
// ---------------------------------------------------------------------------

#define OF_ESRCB 0ul          /* bf16 2048x512  (524288 f) */
#define OF_ETGTB 524288ul     /* bf16 2048x512  */
#define OF_GXF   1048576ul    /* f32 2048x1536  */
#define OF_GXB   4194304ul
#define OF_DGX   7340032ul
#define OF_SRCHB 10485760ul   /* bf16 2048x1024 (1048576 f) */
#define OF_UH    11534336ul   /* f32 2048x512   */
#define OF_DOUT  12582912ul   /* f32 2048x512   */
#define OF_DOB   13631488ul   /* bf16 2048x512  */
#define OF_HF    14155776ul   /* 2*32*512 double buffer */
#define OF_HB    14188544ul
#define OF_HD    14221312ul
#define OF_QS    14254080ul   /* 32*512 */
#define OF_AL    14270464ul   /* 32*64  */
#define OF_LP    14272512ul   /* 2048*256 (125 pairs/row, stride 256) */
#define OF_CON   15296512ul
#define OF_CNT   15298560ul
#define OF_PB    15300608ul   /* bf16 PT: [32][1536][64] (1572864 f) */
#define OF_WF16  16873472ul   /* bf16 1536x512  */
#define OF_WB16  17266688ul
#define OF_WD16  17659904ul   /* bf16 1536x1536 */
#define OF_UW16  18839552ul   /* bf16 512x1024  */
#define OF_OW16  19101696ul   /* bf16 32000x512 */
#define BUF_TOTAL 27293696ul

__device__ __align__(16) float g_buf[BUF_TOTAL];

// grid-barrier state, one counter per 128B line (reset every replay by k_init)
__device__ unsigned g_bar_arr[128];
__device__ volatile unsigned g_bar_rel[128];
// logits row compaction + zero-row logZ
__device__ int g_rows[2048];
__device__ int g_nrows;
__device__ float g_M0, g_L0;

__device__ __forceinline__ float sigm(float x) { return 1.f / (1.f + __expf(-x)); }
__device__ __forceinline__ float dot4(float4 a, float4 b, float acc) {
    acc = fmaf(a.x, b.x, acc); acc = fmaf(a.y, b.y, acc);
    acc = fmaf(a.z, b.z, acc); acc = fmaf(a.w, b.w, acc);
    return acc;
}

__device__ __forceinline__ unsigned smem_u32(const void* p) {
    unsigned a;
    asm("{ .reg .u64 t; cvta.to.shared.u64 t, %1; cvt.u32.u64 %0, t; }"
        : "=r"(a) : "l"(p));
    return a;
}

// cp.async helpers (sm_80+)
#define CP16(dst, src) \
    asm volatile("cp.async.cg.shared.global [%0], [%1], 16;" \
                 :: "r"(dst), "l"(src) : "memory")
#define CP_COMMIT() asm volatile("cp.async.commit_group;" ::: "memory")
#define CP_WAIT(n)  asm volatile("cp.async.wait_group %0;" :: "n"(n) : "memory")

// Software grid barrier (atomic counter + release word). All blocks co-resident.
__device__ __forceinline__ void gridbar(int idx, unsigned e, unsigned nb) {
    __syncthreads();
    if (threadIdx.x == 0) {
        __threadfence();
        unsigned old = atomicAdd(&g_bar_arr[idx * 32], 1u);
        if (old == e * nb + nb - 1u) {
            g_bar_rel[idx * 32] = e + 1u;
        }
        while (g_bar_rel[idx * 32] < e + 1u) {}
        __threadfence();
    }
    __syncthreads();
}

// ---------------------------------------------------------------------------
// k_init: zero hidden states + barrier state; row compaction; logz0
// grid 66 x 256
// ---------------------------------------------------------------------------
__global__ void k_init(const int* __restrict__ tlen, const float* __restrict__ ob) {
    int bid = blockIdx.x, t = threadIdx.x;
    if (bid < 64) {
        int i = bid * 256 + t;
        g_buf[OF_HF + i] = 0.f;
        g_buf[OF_HB + i] = 0.f;
        g_buf[OF_HD + i] = 0.f;
        if (bid == 0 && t < 4) {
            g_bar_arr[t * 32] = 0u;
            g_bar_rel[t * 32] = 0u;
        }
    } else if (bid == 64) {
        __shared__ int offs[32];
        if (t == 0) {
            int a = 0;
            for (int b = 0; b < 32; b++) { offs[b] = a; a += tlen[b]; }
            g_nrows = a;
        }
        __syncthreads();
        for (int i = t; i < 2048; i += 256) g_rows[i] = 2047;
        __syncthreads();
        for (int b = 0; b < 32; b++) {
            int L = tlen[b];
            for (int tc = t; tc < L; tc += 256)
                g_rows[offs[b] + tc] = b * 64 + tc;
        }
    } else {
        __shared__ float red[8];
        int lane = t & 31, w = t >> 5;
        float m = -1e30f;
        for (int i = t; i < 32000; i += 256) m = fmaxf(m, ob[i]);
#pragma unroll
        for (int o = 16; o > 0; o >>= 1)
            m = fmaxf(m, __shfl_xor_sync(0xffffffffu, m, o));
        if (lane == 0) red[w] = m;
        __syncthreads();
        if (t == 0) {
            float v = red[0];
            for (int i = 1; i < 8; i++) v = fmaxf(v, red[i]);
            red[0] = v;
        }
        __syncthreads();
        float M = red[0];
        __syncthreads();
        float l = 0.f;
        for (int i = t; i < 32000; i += 256) l += __expf(ob[i] - M);
#pragma unroll
        for (int o = 16; o > 0; o >>= 1) l += __shfl_xor_sync(0xffffffffu, l, o);
        if (lane == 0) red[w] = l;
        __syncthreads();
        if (t == 0) {
            float s = 0.f;
            for (int i = 0; i < 8; i++) s += red[i];
            g_M0 = M; g_L0 = s;
        }
    }
}

// ---------------------------------------------------------------------------
// k_prep: all fp32->bf16 weight conversions + both embedding gathers
// grid 12224 x 256
// ---------------------------------------------------------------------------
__device__ __forceinline__ uint4 cvt8(float4 a, float4 b) {
    __nv_bfloat162 h0 = __floats2bfloat162_rn(a.x, a.y);
    __nv_bfloat162 h1 = __floats2bfloat162_rn(a.z, a.w);
    __nv_bfloat162 h2 = __floats2bfloat162_rn(b.x, b.y);
    __nv_bfloat162 h3 = __floats2bfloat162_rn(b.z, b.w);
    uint4 u;
    u.x = *(unsigned*)&h0; u.y = *(unsigned*)&h1;
    u.z = *(unsigned*)&h2; u.w = *(unsigned*)&h3;
    return u;
}
__global__ void k_prep(
    const float* __restrict__ eWih_f, const float* __restrict__ eWih_b,
    const float* __restrict__ dWih, const float* __restrict__ U_w,
    const float* __restrict__ out_w,
    const int* __restrict__ src_seqs, const float* __restrict__ src_emb,
    const int* __restrict__ tgt_seqs, const float* __restrict__ tgt_emb)
{
    int bid = blockIdx.x, t = threadIdx.x;
    if (bid < 10176) {
        const float* src; size_t dst; int base;
        if (bid < 384)        { src = eWih_f; dst = OF_WF16; base = 0; }
        else if (bid < 768)   { src = eWih_b; dst = OF_WB16; base = 384; }
        else if (bid < 1920)  { src = dWih;   dst = OF_WD16; base = 768; }
        else if (bid < 2176)  { src = U_w;    dst = OF_UW16; base = 1920; }
        else                  { src = out_w;  dst = OF_OW16; base = 2176; }
        size_t i = (size_t)(bid - base) * 256 + t;
        float4 a = ((const float4*)src)[i*2];
        float4 b = ((const float4*)src)[i*2 + 1];
        ((uint4*)(g_buf + dst))[i] = cvt8(a, b);
    } else {
        int eb = bid - 10176;
        const int* ids; const float* tab; size_t dst;
        if (eb < 1024) { ids = src_seqs; tab = src_emb; dst = OF_ESRCB; }
        else { eb -= 1024; ids = tgt_seqs; tab = tgt_emb; dst = OF_ETGTB; }
        int row = eb * 2 + (t >> 7), lane = t & 127;
        float4 v = ((const float4*)(tab + (size_t)ids[row] * 512))[lane];
        __nv_bfloat162 h0 = __floats2bfloat162_rn(v.x, v.y);
        __nv_bfloat162 h1 = __floats2bfloat162_rn(v.z, v.w);
        uint2 u; u.x = *(unsigned*)&h0; u.y = *(unsigned*)&h1;
        ((uint2*)(g_buf + dst))[(size_t)row * 128 + lane] = u;
    }
}

// ---------------------------------------------------------------------------
// bf16 GEMM core: BM=128 x BN=256 x BK=32, 256 thr (8 warps, 2x4, 64x64/warp).
// cp.async double-buffered smem (stride 40 halves). C = A @ W^T.
// mode: 0 = fp32 store (+bias); 1 = bf16 P-transposed store; 2 = fused
// (max,sumexp) logsumexp partials. dyn smem = 61440 B.
// ---------------------------------------------------------------------------
__device__ __forceinline__ void mm256_body(
    __nv_bfloat16* smh, const __nv_bfloat16* A, int lda,
    const __nv_bfloat16* W, int ldw, const float* bias,
    size_t c_off, int ldc, int K, int mode,
    int bm, int bn, const int* rid, const float* bsh)
{
    int t = threadIdx.x, wid = t >> 5;
    int wm = (wid >> 2) * 64, wn4 = wid & 3;
    unsigned sb = smem_u32(smh);

    wmma::fragment<wmma::accumulator, 16, 16, 16, float> acc[4][4];
#pragma unroll
    for (int i = 0; i < 4; i++)
#pragma unroll
        for (int j = 0; j < 4; j++) wmma::fill_fragment(acc[i][j], 0.f);

    int ar = t >> 1, as2 = (t & 1) * 2;
    const int arow = rid[ar];

#define MM_ISSUE(c) {                                                           \
        int kb = (c) * 32;                                                      \
        unsigned ab = sb + (unsigned)((c) & 1) * 30720u;                        \
        const __nv_bfloat16* sa = A + (size_t)arow * lda + kb + as2 * 8;        \
        unsigned da = ab + (unsigned)ar * 80u + (unsigned)as2 * 16u;            \
        CP16(da, sa); CP16(da + 16u, sa + 8);                                   \
        const __nv_bfloat16* sw = W + (size_t)(bn + t) * ldw + kb;              \
        unsigned db = ab + 10240u + (unsigned)t * 80u;                          \
        CP16(db, sw); CP16(db + 16u, sw + 8);                                   \
        CP16(db + 32u, sw + 16); CP16(db + 48u, sw + 24);                       \
        CP_COMMIT(); }

    MM_ISSUE(0)
    int nk = K / 32;
    for (int c = 0; c < nk; c++) {
        if (c + 1 < nk) { MM_ISSUE(c + 1) CP_WAIT(1); }
        else CP_WAIT(0);
        __syncthreads();
        const __nv_bfloat16* As = smh + (size_t)(c & 1) * 15360;
        const __nv_bfloat16* Bs = As + 5120;
#pragma unroll
        for (int kk = 0; kk < 32; kk += 16) {
            wmma::fragment<wmma::matrix_a, 16, 16, 16, __nv_bfloat16,
                           wmma::row_major> af[4];
            wmma::fragment<wmma::matrix_b, 16, 16, 16, __nv_bfloat16,
                           wmma::col_major> bf[4];
#pragma unroll
            for (int i = 0; i < 4; i++)
                wmma::load_matrix_sync(af[i], As + (wm + i*16) * 40 + kk, 40);
#pragma unroll
            for (int j = 0; j < 4; j++)
                wmma::load_matrix_sync(bf[j], Bs + (wn4*64 + j*16) * 40 + kk, 40);
#pragma unroll
            for (int i = 0; i < 4; i++)
#pragma unroll
                for (int j = 0; j < 4; j++)
                    wmma::mma_sync(acc[i][j], af[i], bf[j], acc[i][j]);
        }
        __syncthreads();
    }
#undef MM_ISSUE

    float* Cs = (float*)smh;
    int r = t >> 1, half = t & 1;
    float M = -1e30f, L = 0.f;
#pragma unroll
    for (int p = 0; p < 4; p++) {
        __syncthreads();
#pragma unroll
        for (int i = 0; i < 4; i++)
            wmma::store_matrix_sync(Cs + (size_t)(wm + i*16) * 68 + wn4 * 16,
                                    acc[i][p], 68, wmma::mem_row_major);
        __syncthreads();
        if (mode == 2) {
            float m = -1e30f, v[32];
#pragma unroll
            for (int pi = 0; pi < 2; pi++) {
                int cc = half * 32 + pi * 16;
                int gc = (cc >> 4) * 64 + p * 16;
#pragma unroll
                for (int u = 0; u < 16; u++) {
                    float x = Cs[(size_t)r * 68 + cc + u] + bsh[gc + u];
                    v[pi*16 + u] = x; m = fmaxf(m, x);
                }
            }
            float l = 0.f;
#pragma unroll
            for (int u = 0; u < 32; u++) l += __expf(v[u] - m);
            float nM = fmaxf(M, m);
            L = L * __expf(M - nM) + l * __expf(m - nM);
            M = nM;
        } else if (mode == 1) {
            int b_ = (bm + r) >> 6, s_ = (bm + r) & 63;
            __nv_bfloat16* Pt = ((__nv_bfloat16*)g_buf) + 2*OF_PB;
#pragma unroll
            for (int pi = 0; pi < 2; pi++) {
                int cc = half * 32 + pi * 16;
                int g0 = bn + (cc >> 4) * 64 + p * 16;
                for (int u = 0; u < 16; u++)
                    Pt[(size_t)b_ * 98304 + (size_t)(g0 + u) * 64 + s_] =
                        __float2bfloat16(Cs[(size_t)r * 68 + cc + u]);
            }
        } else {
#pragma unroll
            for (int pi = 0; pi < 2; pi++) {
                int cc = half * 32 + pi * 16;
                int g0 = bn + (cc >> 4) * 64 + p * 16;
                float* Crow = g_buf + c_off + (size_t)(bm + r) * ldc + g0;
#pragma unroll
                for (int u = 0; u < 16; u += 4) {
                    float4 x = *(float4*)(Cs + (size_t)r * 68 + cc + u);
                    if (bias) {
                        float4 bv = *(const float4*)(bias + g0 + u);
                        x.x += bv.x; x.y += bv.y; x.z += bv.z; x.w += bv.w;
                    }
                    *(float4*)(Crow + u) = x;
                }
            }
        }
    }
    if (mode == 2) {
        float M2 = __shfl_xor_sync(0xffffffffu, M, 1);
        float L2 = __shfl_xor_sync(0xffffffffu, L, 1);
        float nM = fmaxf(M, M2);
        float LL = L * __expf(M - nM) + L2 * __expf(M2 - nM);
        if (half == 0) {
            size_t orow = (size_t)rid[r];
            g_buf[OF_LP + orow * 256 + (size_t)blockIdx.x * 2]     = nM;
            g_buf[OF_LP + orow * 256 + (size_t)blockIdx.x * 2 + 1] = LL;
        }
    }
}

// Generic wrapper: logits (mode2 + row gather)
__global__ __launch_bounds__(256) void k_mm256(
    size_t a_hoff, int lda, size_t w_hoff, int ldw,
    const float* __restrict__ bias, size_t c_off, int ldc, int K,
    int mode, int use_rows)
{
    extern __shared__ __nv_bfloat16 smh[];
    __shared__ int rid[128];
    __shared__ float bsh[256];
    int bm = blockIdx.y * 128, bn = blockIdx.x * 256;
    if (mode == 2 && bm >= g_nrows) return;
    int t = threadIdx.x;
    if (t < 128) rid[t] = use_rows ? g_rows[bm + t] : (bm + t);
    if (mode == 2) bsh[t] = bias[bn + t];
    __syncthreads();
    mm256_body(smh, ((const __nv_bfloat16*)g_buf) + a_hoff, lda,
               ((const __nv_bfloat16*)g_buf) + w_hoff, ldw, bias,
               c_off, ldc, K, mode, bm, bn, rid, bsh);
}

// Fused Uh (x<2, mode0) + P (x>=2, mode1): grid (8, 16)
__global__ __launch_bounds__(256) void k_uhp(const float* __restrict__ U_b)
{
    extern __shared__ __nv_bfloat16 smh[];
    __shared__ int rid[128];
    int bm = blockIdx.y * 128;
    int t = threadIdx.x;
    if (t < 128) rid[t] = bm + t;
    __syncthreads();
    if (blockIdx.x < 2) {
        int bn = blockIdx.x * 256;
        mm256_body(smh, ((const __nv_bfloat16*)g_buf) + 2*OF_SRCHB, 1024,
                   ((const __nv_bfloat16*)g_buf) + 2*OF_UW16, 1024, U_b,
                   OF_UH, 512, 1024, 0, bm, bn, rid, (const float*)0);
    } else {
        int bn = (blockIdx.x - 2) * 256;
        mm256_body(smh, ((const __nv_bfloat16*)g_buf) + 2*OF_SRCHB, 1024,
                   ((const __nv_bfloat16*)g_buf) + 2*OF_WD16 + 512, 1536,
                   (const float*)0, OF_PB, 0, 1024, 1, bm, bn, rid,
                   (const float*)0);
    }
}

// Fused gate pre-GEMMs: seg 0=GXF 1=GXB 2=DGX. grid (18, 16)
__global__ __launch_bounds__(256) void k_gates256(
    const float* __restrict__ bf, const float* __restrict__ bb,
    const float* __restrict__ bd)
{
    extern __shared__ __nv_bfloat16 smh[];
    __shared__ int rid[128];
    int seg = blockIdx.x / 6, xb = blockIdx.x % 6;
    size_t a_hoff = (seg == 2) ? 2*OF_ETGTB : 2*OF_ESRCB;
    size_t w_hoff = (seg == 0) ? 2*OF_WF16 : (seg == 1) ? 2*OF_WB16 : 2*OF_WD16;
    int ldw = (seg == 2) ? 1536 : 512;
    const float* bias = (seg == 0) ? bf : (seg == 1) ? bb : bd;
    size_t c_off = (seg == 0) ? OF_GXF : (seg == 1) ? OF_GXB : OF_DGX;
    int bm = blockIdx.y * 128, bn = xb * 256;
    int t = threadIdx.x;
    if (t < 128) rid[t] = bm + t;
    __syncthreads();
    mm256_body(smh, ((const __nv_bfloat16*)g_buf) + a_hoff, 512,
               ((const __nv_bfloat16*)g_buf) + w_hoff, ldw, bias,
               c_off, 1536, 512, 0, bm, bn, rid, (const float*)0);
}

// ---------------------------------------------------------------------------
// High-ILP gate GEMM inner: thread (rp, j) computes 3 dots of length 512
// against smem-resident weights (stride 516) and smem-resident h (stride 516).
// 6 split accumulator chains, 16 loads in flight per segment.
// ---------------------------------------------------------------------------
__device__ __forceinline__ void gate_dots(
    const float* __restrict__ wr_, const float* __restrict__ wz_,
    const float* __restrict__ wn_, const float* __restrict__ hr_,
    float& arO, float& azO, float& anO)
{
    float ar0=0.f, ar1=0.f, az0=0.f, az1=0.f, an0=0.f, an1=0.f;
#pragma unroll 2
    for (int kq = 0; kq < 32; kq++) {
        int kb = kq * 16;
        float4 h0 = *(const float4*)(hr_ + kb);
        float4 h1 = *(const float4*)(hr_ + kb + 4);
        float4 h2 = *(const float4*)(hr_ + kb + 8);
        float4 h3 = *(const float4*)(hr_ + kb + 12);
        float4 r0 = *(const float4*)(wr_ + kb);
        float4 r1 = *(const float4*)(wr_ + kb + 4);
        float4 r2 = *(const float4*)(wr_ + kb + 8);
        float4 r3 = *(const float4*)(wr_ + kb + 12);
        float4 z0 = *(const float4*)(wz_ + kb);
        float4 z1 = *(const float4*)(wz_ + kb + 4);
        float4 z2 = *(const float4*)(wz_ + kb + 8);
        float4 z3 = *(const float4*)(wz_ + kb + 12);
        float4 n0 = *(const float4*)(wn_ + kb);
        float4 n1 = *(const float4*)(wn_ + kb + 4);
        float4 n2 = *(const float4*)(wn_ + kb + 8);
        float4 n3 = *(const float4*)(wn_ + kb + 12);
        ar0 = dot4(h0, r0, ar0); ar1 = dot4(h1, r1, ar1);
        az0 = dot4(h0, z0, az0); az1 = dot4(h1, z1, az1);
        an0 = dot4(h0, n0, an0); an1 = dot4(h1, n1, an1);
        ar0 = dot4(h2, r2, ar0); ar1 = dot4(h3, r3, ar1);
        az0 = dot4(h2, z2, az0); az1 = dot4(h3, z3, az1);
        an0 = dot4(h2, n2, an0); an1 = dot4(h3, n3, an1);
    }
    arO = ar0 + ar1; azO = az0 + az1; anO = an0 + an1;
}

// ---------------------------------------------------------------------------
// Persistent encoder: 128 blocks x 256 thr, 64 steps, barrier idx 0.
// Whh slice (24x512) + full h (32x512) smem-resident. dyn smem 115584 B.
// ---------------------------------------------------------------------------
__global__ __launch_bounds__(256) void k_enc_all(
    const float* __restrict__ Whh_f, const float* __restrict__ bhh_f,
    const float* __restrict__ Whh_b, const float* __restrict__ bhh_b,
    const int* __restrict__ slen)
{
    extern __shared__ float dsm[];
    float* wsh = dsm;               // [24][516]
    float* Hsd = dsm + 24 * 516;    // [32][516]
    int bid = blockIdx.x;
    int dir = bid >> 6;
    int j0 = (bid & 63) * 8;
    const float* Whh = dir ? Whh_b : Whh_f;
    const float* bhh = dir ? bhh_b : bhh_f;
    size_t hb = dir ? OF_HB : OF_HF;
    const float* gx = g_buf + (dir ? OF_GXB : OF_GXF);
    __nv_bfloat16* srch = ((__nv_bfloat16*)g_buf) + 2*OF_SRCHB;
    int t = threadIdx.x;

    for (int i = t; i < 24 * 128; i += 256) {
        int wr = i >> 7, c4 = (i & 127) * 4;
        int gw = (wr >> 3) * 512 + j0 + (wr & 7);
        *(float4*)&wsh[wr * 516 + c4] = *(const float4*)(Whh + (size_t)gw * 512 + c4);
    }

    int rp = t >> 3, j = t & 7, jg = j0 + j;
    float br = bhh[jg], bz = bhh[512 + jg], bnn = bhh[1024 + jg];
    int sl = slen[rp];
    const float* wr_ = wsh + (size_t)j * 516;
    const float* wz_ = wsh + (size_t)(8 + j) * 516;
    const float* wn_ = wsh + (size_t)(16 + j) * 516;
    const float* hr_ = Hsd + (size_t)rp * 516;

    for (int s = 0; s < 64; s++) {
        if (s > 0) gridbar(0, (unsigned)(s - 1), 128);
        else __syncthreads();
        int pin = s & 1;
        const float* hin = g_buf + hb + (size_t)pin * 16384;
        float* hout = g_buf + hb + (size_t)(pin ^ 1) * 16384;
        int tt = dir ? (63 - s) : s;

        // stage full h (32x512) in smem once
#pragma unroll
        for (int i = 0; i < 2; i++) {
            int vec = t + 256 * i;       // 0..511 float4s
            int rr = vec >> 4, kv = vec & 15;
            *(float4*)&Hsd[rr * 516 + kv * 4] =
                *(const float4*)(hin + (size_t)rr * 512 + kv * 4);
        }
        __syncthreads();

        float ar, az, an;
        gate_dots(wr_, wz_, wn_, hr_, ar, az, an);

        size_t grow = (size_t)rp * 64 + tt;
        float gxr = gx[grow*1536 + jg];
        float gxz = gx[grow*1536 + 512 + jg];
        float gxn = gx[grow*1536 + 1024 + jg];
        float rr = sigm(gxr + ar + br);
        float zz = sigm(gxz + az + bz);
        float nn = tanhf(gxn + rr * (an + bnn));
        float hold = hin[(size_t)rp*512 + jg];
        float hnew = (1.f - zz) * nn + zz * hold;
        bool m = tt < sl;
        hout[(size_t)rp*512 + jg] = m ? hnew : hold;
        srch[grow*1024 + (size_t)dir*512 + jg] = __float2bfloat16(m ? hnew : 0.f);
    }
}

// ---------------------------------------------------------------------------
// Persistent decoder: 128 blocks x 256 thr, 64 steps (R12 structure + ILP G).
//   blocks   0-31 : A — Uh[b] smem-resident; scores/softmax; publish alpha
//   blocks  32-63 : Q — qs = A_W-slice @ h (fp32 A_W smem-resident)
//   blocks 64-127 : G — gate_dots (smem Whh + smem h); ctx from bf16 P^T; GRU
// barriers: idx1 = h ready (128), idx2 = qs ready (A+Q, 64), idx3 = alpha (128)
// dyn smem = 131072 B (A: Uh 64x512 f32; G: 24x516 W + 32x516 h)
// ---------------------------------------------------------------------------
__global__ __launch_bounds__(256) void k_dec_all(
    const float* __restrict__ A_W, const float* __restrict__ A_b,
    const float* __restrict__ A_v, const float* __restrict__ Whh,
    const float* __restrict__ bhh, const int* __restrict__ slen,
    const int* __restrict__ tlen)
{
    extern __shared__ float dsm[];
    __shared__ float es[64];
    __shared__ float als[32][64];

    int bid = blockIdx.x;
    int t = threadIdx.x;
    int lane = t & 31;
    bool isA = bid < 32;
    bool isQ = (bid >= 32 && bid < 64);
    bool isG = bid >= 64;
    int b   = bid;
    int qid = bid - 32;
    int j0  = (bid - 64) * 8;
    float* wsh = dsm;               // G: [24][516]
    float* Hsd = dsm + 24 * 516;    // G: [32][516]

    float avr[16], qb0 = 0.f, qb1 = 0.f;
    if (isA) {
        for (int i = t; i < 8192; i += 256)
            *(float4*)&dsm[(size_t)i*4] =
                *(const float4*)(g_buf + OF_UH + (size_t)b*32768 + (size_t)i*4);
#pragma unroll
        for (int k = 0; k < 16; k++) avr[k] = A_v[lane + 32*k];
    }
    if (isQ) {
        for (int i = t; i < 16 * 128; i += 256) {
            int r = i >> 7, c4 = (i & 127) * 4;
            *(float4*)&dsm[r * 516 + c4] =
                *(const float4*)(A_W + (size_t)(qid*16 + r) * 512 + c4);
        }
        qb0 = A_b[qid*16 + (t & 15)];
        qb1 = A_b[qid*16 + ((t + 256) & 15)];
    }
    if (isG) {
        for (int i = t; i < 24 * 128; i += 256) {
            int wr = i >> 7, c4 = (i & 127) * 4;
            int gw = (wr >> 3) * 512 + j0 + (wr & 7);
            *(float4*)&wsh[wr * 516 + c4] =
                *(const float4*)(Whh + (size_t)gw * 512 + c4);
        }
    }
    __syncthreads();

    int rp = t >> 3, j = t & 7, jg = j0 + j;
    float br = 0.f, bz = 0.f, bnn = 0.f;
    int tl = 64;
    if (isG) {
        br = bhh[jg]; bz = bhh[512 + jg]; bnn = bhh[1024 + jg];
        tl = tlen[rp];
    }
    int sl = isA ? slen[b] : 0;
    const __nv_bfloat16* Pt = ((const __nv_bfloat16*)g_buf) + 2*OF_PB;
    __nv_bfloat16* dob = ((__nv_bfloat16*)g_buf) + 2*OF_DOB;
    const float* wr_ = wsh + (size_t)j * 516;
    const float* wz_ = wsh + (size_t)(8 + j) * 516;
    const float* wn_ = wsh + (size_t)(16 + j) * 516;
    const float* hr_ = Hsd + (size_t)rp * 516;

    for (int step = 0; step < 64; step++) {
        if (step > 0) gridbar(1, (unsigned)(step - 1), 128);   // h published
        int pin = step & 1;
        const float* hin = g_buf + OF_HD + (size_t)pin * 16384;
        float* hout = g_buf + OF_HD + (size_t)(pin ^ 1) * 16384;

        // ---- Q: qs = A_W @ h ----
        if (isQ) {
#pragma unroll
            for (int p = 0; p < 2; p++) {
                int pr = t + p * 256;
                int bb = pr >> 4, jj = pr & 15;
                const float* hrow = hin + (size_t)bb * 512;
                float acc = p ? qb1 : qb0;
                for (int k = 0; k < 512; k += 4)
                    acc = dot4(*(const float4*)&dsm[(size_t)jj*516 + k],
                               *(const float4*)(hrow + k), acc);
                g_buf[OF_QS + (size_t)bb * 512 + qid*16 + jj] = acc;
            }
        }
        if (bid < 64) gridbar(2, (unsigned)step, 64);          // qs ready (A+Q)

        // ---- A: scores + softmax -> alpha ----
        if (isA) {
            float qr[16];
#pragma unroll
            for (int k = 0; k < 16; k++)
                qr[k] = g_buf[OF_QS + (size_t)b*512 + lane + 32*k];
            int w = t >> 5;
#pragma unroll
            for (int si = 0; si < 8; si++) {
                int s = w*8 + si;
                float acc = 0.f;
#pragma unroll
                for (int k = 0; k < 16; k++) {
                    float x = dsm[(size_t)s*512 + lane + 32*k] + qr[k];
                    float th;
                    asm("tanh.approx.f32 %0, %1;" : "=f"(th) : "f"(x));
                    acc = fmaf(avr[k], th, acc);
                }
#pragma unroll
                for (int o = 16; o > 0; o >>= 1)
                    acc += __shfl_xor_sync(0xffffffffu, acc, o);
                if (lane == 0) es[s] = (s < sl) ? acc : acc - 1e9f;
            }
            __syncthreads();
            if (t < 32) {
                float a0 = es[t], a1 = es[t + 32];
                float m = fmaxf(a0, a1);
#pragma unroll
                for (int o = 16; o > 0; o >>= 1)
                    m = fmaxf(m, __shfl_xor_sync(0xffffffffu, m, o));
                float e0 = __expf(a0 - m), e1 = __expf(a1 - m);
                float sum = e0 + e1;
#pragma unroll
                for (int o = 16; o > 0; o >>= 1)
                    sum += __shfl_xor_sync(0xffffffffu, sum, o);
                es[t] = e0 / sum; es[t + 32] = e1 / sum;
            }
            __syncthreads();
            if (t < 64) g_buf[OF_AL + (size_t)b*64 + t] = es[t];
        }

        // ---- G: gate dots (overlaps Q/A; skips bar idx2) ----
        float ar = 0.f, az = 0.f, an = 0.f;
        if (isG) {
#pragma unroll
            for (int i = 0; i < 2; i++) {
                int vec = t + 256 * i;
                int rr = vec >> 4, kv = vec & 15;
                *(float4*)&Hsd[rr * 516 + kv * 4] =
                    *(const float4*)(hin + (size_t)rr * 512 + kv * 4);
            }
            __syncthreads();
            gate_dots(wr_, wz_, wn_, hr_, ar, az, an);
        }
        gridbar(3, (unsigned)step, 128);                       // alpha ready

        // ---- G: ctx from bf16 P^T + pointwise GRU ----
        if (isG) {
            for (int i = t; i < 2048; i += 256)
                als[i >> 6][i & 63] = g_buf[OF_AL + i];
            __syncthreads();
            float cr = 0.f, cz = 0.f, cn = 0.f;
            const uint4* p0 = (const uint4*)(Pt + (size_t)rp*98304 + (size_t)jg*64);
            const uint4* p1 = (const uint4*)(Pt + (size_t)rp*98304 + (size_t)(512 + jg)*64);
            const uint4* p2 = (const uint4*)(Pt + (size_t)rp*98304 + (size_t)(1024 + jg)*64);
#pragma unroll
            for (int q = 0; q < 8; q++) {
                uint4 v0 = p0[q], v1 = p1[q], v2 = p2[q];
                const __nv_bfloat16* h0 = (const __nv_bfloat16*)&v0;
                const __nv_bfloat16* h1 = (const __nv_bfloat16*)&v1;
                const __nv_bfloat16* h2 = (const __nv_bfloat16*)&v2;
#pragma unroll
                for (int u = 0; u < 8; u++) {
                    float al = als[rp][q*8 + u];
                    cr = fmaf(al, __bfloat162float(h0[u]), cr);
                    cz = fmaf(al, __bfloat162float(h1[u]), cz);
                    cn = fmaf(al, __bfloat162float(h2[u]), cn);
                }
            }
            size_t grow = (size_t)rp*64 + step;
            const float* gx = g_buf + OF_DGX + grow*1536;
            float rr = sigm(gx[jg]        + cr + ar + br);
            float zz = sigm(gx[512 + jg]  + cz + az + bz);
            float nn = tanhf(gx[1024 + jg] + cn + rr * (an + bnn));
            float hold = hin[(size_t)rp*512 + jg];
            float hnew = (1.f - zz) * nn + zz * hold;
            bool m = step < tl;
            float o = m ? hnew : 0.f;
            hout[(size_t)rp*512 + jg] = m ? hnew : hold;
            g_buf[OF_DOUT + grow*512 + jg] = o;
            dob[grow*512 + jg] = __float2bfloat16(o);
        }
    }
}

// ---------------------------------------------------------------------------
// Per-row: combine partials (live rows) or shared logZ0 (zero rows)
// ---------------------------------------------------------------------------
__global__ __launch_bounds__(256) void k_combine(
    const int* __restrict__ tgt, const float* __restrict__ out_w,
    const float* __restrict__ out_b, const int* __restrict__ tlen)
{
    int row = blockIdx.x * 8 + (threadIdx.x >> 5);
    int lane = threadIdx.x & 31;
    int b = row >> 6, tc = row & 63;
    int goal = (tc < 63) ? tgt[b*64 + tc + 1] : 0;
    float contrib = 0.f, cnt = 0.f;
    if (goal != 0) {
        bool live = tc < tlen[b];
        float M, L, d = 0.f;
        if (live) {
            const float* p = g_buf + OF_LP + (size_t)row * 256;
            M = -1e30f;
            for (int c = lane; c < 125; c += 32) M = fmaxf(M, p[c*2]);
#pragma unroll
            for (int o = 16; o > 0; o >>= 1)
                M = fmaxf(M, __shfl_xor_sync(0xffffffffu, M, o));
            L = 0.f;
            for (int c = lane; c < 125; c += 32) L += p[c*2+1] * __expf(p[c*2] - M);
#pragma unroll
            for (int o = 16; o > 0; o >>= 1)
                L += __shfl_xor_sync(0xffffffffu, L, o);
            const float* x = g_buf + OF_DOUT + (size_t)row * 512;
            const float* wrow = out_w + (size_t)goal * 512;
            for (int k = lane; k < 512; k += 32) d = fmaf(x[k], wrow[k], d);
#pragma unroll
            for (int o = 16; o > 0; o >>= 1)
                d += __shfl_xor_sync(0xffffffffu, d, o);
        } else {
            M = g_M0; L = g_L0;
        }
        contrib = (d + out_b[goal]) - (M + logf(L));
        cnt = 1.f;
    }
    if (lane == 0) {
        g_buf[OF_CON + row] = contrib;
        g_buf[OF_CNT + row] = cnt;
    }
}

// ---------------------------------------------------------------------------
// Final deterministic reduce -> loss
// ---------------------------------------------------------------------------
__global__ void k_final(float* out) {
    __shared__ float sc[1024], sn[1024];
    int t = threadIdx.x;
    sc[t] = g_buf[OF_CON + t] + g_buf[OF_CON + 1024 + t];
    sn[t] = g_buf[OF_CNT + t] + g_buf[OF_CNT + 1024 + t];
    __syncthreads();
    for (int o = 512; o > 0; o >>= 1) {
        if (t < o) { sc[t] += sc[t+o]; sn[t] += sn[t+o]; }
        __syncthreads();
    }
    if (t == 0) out[0] = -sc[0] / sn[0];
}

// ---------------------------------------------------------------------------
// Host orchestration (graph-capturable: kernel launches only, default stream)
// ---------------------------------------------------------------------------
extern "C" void kernel_launch(void* const* d_in, const int* in_sizes, int n_in,
                              void* d_out, int out_size)
{
    const int*   src_seqs = (const int*)  d_in[0];
    const int*   src_len  = (const int*)  d_in[1];
    const int*   tgt_seqs = (const int*)  d_in[2];
    const int*   tgt_len  = (const int*)  d_in[3];
    const float* src_emb  = (const float*)d_in[4];
    const float* eWih_f   = (const float*)d_in[5];
    const float* eWhh_f   = (const float*)d_in[6];
    const float* ebih_f   = (const float*)d_in[7];
    const float* ebhh_f   = (const float*)d_in[8];
    const float* eWih_b   = (const float*)d_in[9];
    const float* eWhh_b   = (const float*)d_in[10];
    const float* ebih_b   = (const float*)d_in[11];
    const float* ebhh_b   = (const float*)d_in[12];
    const float* tgt_emb  = (const float*)d_in[13];
    const float* dWih     = (const float*)d_in[14];
    const float* dWhh     = (const float*)d_in[15];
    const float* dbih     = (const float*)d_in[16];
    const float* dbhh     = (const float*)d_in[17];
    const float* U_w      = (const float*)d_in[18];
    const float* U_b      = (const float*)d_in[19];
    const float* A_W      = (const float*)d_in[20];
    const float* A_b      = (const float*)d_in[21];
    const float* A_v      = (const float*)d_in[22];
    const float* out_w    = (const float*)d_in[23];
    const float* out_b    = (const float*)d_in[24];

    cudaFuncSetAttribute(k_enc_all,  cudaFuncAttributeMaxDynamicSharedMemorySize, 115584);
    cudaFuncSetAttribute(k_dec_all,  cudaFuncAttributeMaxDynamicSharedMemorySize, 131072);
    cudaFuncSetAttribute(k_mm256,    cudaFuncAttributeMaxDynamicSharedMemorySize, 61440);
    cudaFuncSetAttribute(k_uhp,      cudaFuncAttributeMaxDynamicSharedMemorySize, 61440);
    cudaFuncSetAttribute(k_gates256, cudaFuncAttributeMaxDynamicSharedMemorySize, 61440);

    // 1: init (zero h, barrier state, row compaction, logZ0)
    k_init<<<66, 256>>>(tgt_len, out_b);
    // 2: all weight cvt + embeds in one launch
    k_prep<<<12224, 256>>>(eWih_f, eWih_b, dWih, U_w, out_w,
                           src_seqs, src_emb, tgt_seqs, tgt_emb);
    // 3: fused gate pre-GEMMs (GXF, GXB, DGX)
    k_gates256<<<dim3(18, 16), 256, 61440>>>(ebih_f, ebih_b, dbih);
    // 4: persistent bidirectional encoder
    k_enc_all<<<128, 256, 115584>>>(eWhh_f, ebhh_f, eWhh_b, ebhh_b, src_len);
    // 5: fused Uh + P
    k_uhp<<<dim3(8, 16), 256, 61440>>>(U_b);
    // 6: persistent decoder (profiled by ncu -s 5 -c 1)
    k_dec_all<<<128, 256, 131072>>>(A_W, A_b, A_v, dWhh, dbhh, src_len, tgt_len);
    // 7: logits with fused log-softmax partials
    k_mm256<<<dim3(125, 16), 256, 61440>>>(2*OF_DOB, 512, 2*OF_OW16, 512,
                                           out_b, 0, 0, 512, 2, 1);
    // 8-9: combine + final reduce
    k_combine<<<256, 256>>>(tgt_seqs, out_w, out_b, tgt_len);
    k_final<<<1, 1024>>>((float*)d_out);
}

// round 16
// speedup vs baseline: 1.3164x; 1.1274x over previous
#include <cuda_runtime.h>
#include <cuda_bf16.h>
#include <mma.h>
#include <math.h>

using namespace nvcuda;

// ---------------------------------------------------------------------------
// Problem constants: B=32, S=T=64, E=H=512, G=3H=1536, V=32000
// ---------------------------------------------------------------------------

#define OF_ESRCB 0ul          /* bf16 2048x512  (524288 f) */
#define OF_ETGTB 524288ul     /* bf16 2048x512  */
#define OF_GXF   1048576ul    /* f32 2048x1536  */
#define OF_GXB   4194304ul
#define OF_DGX   7340032ul
#define OF_SRCHB 10485760ul   /* bf16 2048x1024 (1048576 f) */
#define OF_UH    11534336ul   /* f32 2048x512   */
#define OF_DOUT  12582912ul   /* f32 2048x512   */
#define OF_DOB   13631488ul   /* bf16 2048x512  */
#define OF_HF    14155776ul   /* 2*32*512 double buffer */
#define OF_HB    14188544ul
#define OF_HD    14221312ul
#define OF_QS    14254080ul   /* 32*512 */
#define OF_AL    14270464ul   /* 32*64  */
#define OF_LP    14272512ul   /* 2048*256 (125 pairs/row, stride 256) */
#define OF_CON   15296512ul
#define OF_CNT   15298560ul
#define OF_PB    15300608ul   /* bf16 PT: [32][1536][64] (1572864 f) */
#define OF_WF16  16873472ul   /* bf16 1536x512  */
#define OF_WB16  17266688ul
#define OF_WD16  17659904ul   /* bf16 1536x1536 */
#define OF_UW16  18839552ul   /* bf16 512x1024  */
#define OF_OW16  19101696ul   /* bf16 32000x512 */
#define BUF_TOTAL 27293696ul

__device__ __align__(16) float g_buf[BUF_TOTAL];

// grid-barrier state, one counter per 128B line (reset every replay by k_init)
__device__ unsigned g_bar_arr[128];
__device__ volatile unsigned g_bar_rel[128];
// logits row compaction + zero-row logZ
__device__ int g_rows[2048];
__device__ int g_nrows;
__device__ float g_M0, g_L0;

__device__ __forceinline__ float sigm(float x) { return 1.f / (1.f + __expf(-x)); }
__device__ __forceinline__ float dot4(float4 a, float4 b, float acc) {
    acc = fmaf(a.x, b.x, acc); acc = fmaf(a.y, b.y, acc);
    acc = fmaf(a.z, b.z, acc); acc = fmaf(a.w, b.w, acc);
    return acc;
}

__device__ __forceinline__ unsigned smem_u32(const void* p) {
    unsigned a;
    asm("{ .reg .u64 t; cvta.to.shared.u64 t, %1; cvt.u32.u64 %0, t; }"
        : "=r"(a) : "l"(p));
    return a;
}

// cp.async helpers (sm_80+)
#define CP16(dst, src) \
    asm volatile("cp.async.cg.shared.global [%0], [%1], 16;" \
                 :: "r"(dst), "l"(src) : "memory")
#define CP_COMMIT() asm volatile("cp.async.commit_group;" ::: "memory")
#define CP_WAIT(n)  asm volatile("cp.async.wait_group %0;" :: "n"(n) : "memory")

// Software grid barrier (atomic counter + release word). All blocks co-resident.
__device__ __forceinline__ void gridbar(int idx, unsigned e, unsigned nb) {
    __syncthreads();
    if (threadIdx.x == 0) {
        __threadfence();
        unsigned old = atomicAdd(&g_bar_arr[idx * 32], 1u);
        if (old == e * nb + nb - 1u) {
            g_bar_rel[idx * 32] = e + 1u;
        }
        while (g_bar_rel[idx * 32] < e + 1u) {}
        __threadfence();
    }
    __syncthreads();
}

// ---------------------------------------------------------------------------
// k_init: zero hidden states + barrier state; row compaction; logz0
// grid 66 x 256
// ---------------------------------------------------------------------------
__global__ void k_init(const int* __restrict__ tlen, const float* __restrict__ ob) {
    int bid = blockIdx.x, t = threadIdx.x;
    if (bid < 64) {
        int i = bid * 256 + t;
        g_buf[OF_HF + i] = 0.f;
        g_buf[OF_HB + i] = 0.f;
        g_buf[OF_HD + i] = 0.f;
        if (bid == 0 && t < 4) {
            g_bar_arr[t * 32] = 0u;
            g_bar_rel[t * 32] = 0u;
        }
    } else if (bid == 64) {
        __shared__ int offs[32];
        if (t == 0) {
            int a = 0;
            for (int b = 0; b < 32; b++) { offs[b] = a; a += tlen[b]; }
            g_nrows = a;
        }
        __syncthreads();
        for (int i = t; i < 2048; i += 256) g_rows[i] = 2047;
        __syncthreads();
        for (int b = 0; b < 32; b++) {
            int L = tlen[b];
            for (int tc = t; tc < L; tc += 256)
                g_rows[offs[b] + tc] = b * 64 + tc;
        }
    } else {
        __shared__ float red[8];
        int lane = t & 31, w = t >> 5;
        float m = -1e30f;
        for (int i = t; i < 32000; i += 256) m = fmaxf(m, ob[i]);
#pragma unroll
        for (int o = 16; o > 0; o >>= 1)
            m = fmaxf(m, __shfl_xor_sync(0xffffffffu, m, o));
        if (lane == 0) red[w] = m;
        __syncthreads();
        if (t == 0) {
            float v = red[0];
            for (int i = 1; i < 8; i++) v = fmaxf(v, red[i]);
            red[0] = v;
        }
        __syncthreads();
        float M = red[0];
        __syncthreads();
        float l = 0.f;
        for (int i = t; i < 32000; i += 256) l += __expf(ob[i] - M);
#pragma unroll
        for (int o = 16; o > 0; o >>= 1) l += __shfl_xor_sync(0xffffffffu, l, o);
        if (lane == 0) red[w] = l;
        __syncthreads();
        if (t == 0) {
            float s = 0.f;
            for (int i = 0; i < 8; i++) s += red[i];
            g_M0 = M; g_L0 = s;
        }
    }
}

// ---------------------------------------------------------------------------
// k_prep: all fp32->bf16 weight conversions + both embedding gathers
// grid 12224 x 256
// ---------------------------------------------------------------------------
__device__ __forceinline__ uint4 cvt8(float4 a, float4 b) {
    __nv_bfloat162 h0 = __floats2bfloat162_rn(a.x, a.y);
    __nv_bfloat162 h1 = __floats2bfloat162_rn(a.z, a.w);
    __nv_bfloat162 h2 = __floats2bfloat162_rn(b.x, b.y);
    __nv_bfloat162 h3 = __floats2bfloat162_rn(b.z, b.w);
    uint4 u;
    u.x = *(unsigned*)&h0; u.y = *(unsigned*)&h1;
    u.z = *(unsigned*)&h2; u.w = *(unsigned*)&h3;
    return u;
}
__global__ void k_prep(
    const float* __restrict__ eWih_f, const float* __restrict__ eWih_b,
    const float* __restrict__ dWih, const float* __restrict__ U_w,
    const float* __restrict__ out_w,
    const int* __restrict__ src_seqs, const float* __restrict__ src_emb,
    const int* __restrict__ tgt_seqs, const float* __restrict__ tgt_emb)
{
    int bid = blockIdx.x, t = threadIdx.x;
    if (bid < 10176) {
        const float* src; size_t dst; int base;
        if (bid < 384)        { src = eWih_f; dst = OF_WF16; base = 0; }
        else if (bid < 768)   { src = eWih_b; dst = OF_WB16; base = 384; }
        else if (bid < 1920)  { src = dWih;   dst = OF_WD16; base = 768; }
        else if (bid < 2176)  { src = U_w;    dst = OF_UW16; base = 1920; }
        else                  { src = out_w;  dst = OF_OW16; base = 2176; }
        size_t i = (size_t)(bid - base) * 256 + t;
        float4 a = ((const float4*)src)[i*2];
        float4 b = ((const float4*)src)[i*2 + 1];
        ((uint4*)(g_buf + dst))[i] = cvt8(a, b);
    } else {
        int eb = bid - 10176;
        const int* ids; const float* tab; size_t dst;
        if (eb < 1024) { ids = src_seqs; tab = src_emb; dst = OF_ESRCB; }
        else { eb -= 1024; ids = tgt_seqs; tab = tgt_emb; dst = OF_ETGTB; }
        int row = eb * 2 + (t >> 7), lane = t & 127;
        float4 v = ((const float4*)(tab + (size_t)ids[row] * 512))[lane];
        __nv_bfloat162 h0 = __floats2bfloat162_rn(v.x, v.y);
        __nv_bfloat162 h1 = __floats2bfloat162_rn(v.z, v.w);
        uint2 u; u.x = *(unsigned*)&h0; u.y = *(unsigned*)&h1;
        ((uint2*)(g_buf + dst))[(size_t)row * 128 + lane] = u;
    }
}

// ---------------------------------------------------------------------------
// bf16 GEMM core: BM=128 x BN=256 x BK=32, 256 thr (8 warps, 2x4, 64x64/warp).
// cp.async double-buffered smem (stride 40 halves). C = A @ W^T.
// mode: 0 = fp32 store (+bias); 1 = bf16 P-transposed store; 2 = fused
// (max,sumexp) logsumexp partials. dyn smem = 61440 B.
// ---------------------------------------------------------------------------
__device__ __forceinline__ void mm256_body(
    __nv_bfloat16* smh, const __nv_bfloat16* A, int lda,
    const __nv_bfloat16* W, int ldw, const float* bias,
    size_t c_off, int ldc, int K, int mode,
    int bm, int bn, const int* rid, const float* bsh)
{
    int t = threadIdx.x, wid = t >> 5;
    int wm = (wid >> 2) * 64, wn4 = wid & 3;
    unsigned sb = smem_u32(smh);

    wmma::fragment<wmma::accumulator, 16, 16, 16, float> acc[4][4];
#pragma unroll
    for (int i = 0; i < 4; i++)
#pragma unroll
        for (int j = 0; j < 4; j++) wmma::fill_fragment(acc[i][j], 0.f);

    int ar = t >> 1, as2 = (t & 1) * 2;
    const int arow = rid[ar];

#define MM_ISSUE(c) {                                                           \
        int kb = (c) * 32;                                                      \
        unsigned ab = sb + (unsigned)((c) & 1) * 30720u;                        \
        const __nv_bfloat16* sa = A + (size_t)arow * lda + kb + as2 * 8;        \
        unsigned da = ab + (unsigned)ar * 80u + (unsigned)as2 * 16u;            \
        CP16(da, sa); CP16(da + 16u, sa + 8);                                   \
        const __nv_bfloat16* sw = W + (size_t)(bn + t) * ldw + kb;              \
        unsigned db = ab + 10240u + (unsigned)t * 80u;                          \
        CP16(db, sw); CP16(db + 16u, sw + 8);                                   \
        CP16(db + 32u, sw + 16); CP16(db + 48u, sw + 24);                       \
        CP_COMMIT(); }

    MM_ISSUE(0)
    int nk = K / 32;
    for (int c = 0; c < nk; c++) {
        if (c + 1 < nk) { MM_ISSUE(c + 1) CP_WAIT(1); }
        else CP_WAIT(0);
        __syncthreads();
        const __nv_bfloat16* As = smh + (size_t)(c & 1) * 15360;
        const __nv_bfloat16* Bs = As + 5120;
#pragma unroll
        for (int kk = 0; kk < 32; kk += 16) {
            wmma::fragment<wmma::matrix_a, 16, 16, 16, __nv_bfloat16,
                           wmma::row_major> af[4];
            wmma::fragment<wmma::matrix_b, 16, 16, 16, __nv_bfloat16,
                           wmma::col_major> bf[4];
#pragma unroll
            for (int i = 0; i < 4; i++)
                wmma::load_matrix_sync(af[i], As + (wm + i*16) * 40 + kk, 40);
#pragma unroll
            for (int j = 0; j < 4; j++)
                wmma::load_matrix_sync(bf[j], Bs + (wn4*64 + j*16) * 40 + kk, 40);
#pragma unroll
            for (int i = 0; i < 4; i++)
#pragma unroll
                for (int j = 0; j < 4; j++)
                    wmma::mma_sync(acc[i][j], af[i], bf[j], acc[i][j]);
        }
        __syncthreads();
    }
#undef MM_ISSUE

    float* Cs = (float*)smh;
    int r = t >> 1, half = t & 1;
    float M = -1e30f, L = 0.f;
#pragma unroll
    for (int p = 0; p < 4; p++) {
        __syncthreads();
#pragma unroll
        for (int i = 0; i < 4; i++)
            wmma::store_matrix_sync(Cs + (size_t)(wm + i*16) * 68 + wn4 * 16,
                                    acc[i][p], 68, wmma::mem_row_major);
        __syncthreads();
        if (mode == 2) {
            float m = -1e30f, v[32];
#pragma unroll
            for (int pi = 0; pi < 2; pi++) {
                int cc = half * 32 + pi * 16;
                int gc = (cc >> 4) * 64 + p * 16;
#pragma unroll
                for (int u = 0; u < 16; u++) {
                    float x = Cs[(size_t)r * 68 + cc + u] + bsh[gc + u];
                    v[pi*16 + u] = x; m = fmaxf(m, x);
                }
            }
            float l = 0.f;
#pragma unroll
            for (int u = 0; u < 32; u++) l += __expf(v[u] - m);
            float nM = fmaxf(M, m);
            L = L * __expf(M - nM) + l * __expf(m - nM);
            M = nM;
        } else if (mode == 1) {
            int b_ = (bm + r) >> 6, s_ = (bm + r) & 63;
            __nv_bfloat16* Pt = ((__nv_bfloat16*)g_buf) + 2*OF_PB;
#pragma unroll
            for (int pi = 0; pi < 2; pi++) {
                int cc = half * 32 + pi * 16;
                int g0 = bn + (cc >> 4) * 64 + p * 16;
                for (int u = 0; u < 16; u++)
                    Pt[(size_t)b_ * 98304 + (size_t)(g0 + u) * 64 + s_] =
                        __float2bfloat16(Cs[(size_t)r * 68 + cc + u]);
            }
        } else {
#pragma unroll
            for (int pi = 0; pi < 2; pi++) {
                int cc = half * 32 + pi * 16;
                int g0 = bn + (cc >> 4) * 64 + p * 16;
                float* Crow = g_buf + c_off + (size_t)(bm + r) * ldc + g0;
#pragma unroll
                for (int u = 0; u < 16; u += 4) {
                    float4 x = *(float4*)(Cs + (size_t)r * 68 + cc + u);
                    if (bias) {
                        float4 bv = *(const float4*)(bias + g0 + u);
                        x.x += bv.x; x.y += bv.y; x.z += bv.z; x.w += bv.w;
                    }
                    *(float4*)(Crow + u) = x;
                }
            }
        }
    }
    if (mode == 2) {
        float M2 = __shfl_xor_sync(0xffffffffu, M, 1);
        float L2 = __shfl_xor_sync(0xffffffffu, L, 1);
        float nM = fmaxf(M, M2);
        float LL = L * __expf(M - nM) + L2 * __expf(M2 - nM);
        if (half == 0) {
            size_t orow = (size_t)rid[r];
            g_buf[OF_LP + orow * 256 + (size_t)blockIdx.x * 2]     = nM;
            g_buf[OF_LP + orow * 256 + (size_t)blockIdx.x * 2 + 1] = LL;
        }
    }
}

// Generic wrapper: logits (mode2 + row gather)
__global__ __launch_bounds__(256) void k_mm256(
    size_t a_hoff, int lda, size_t w_hoff, int ldw,
    const float* __restrict__ bias, size_t c_off, int ldc, int K,
    int mode, int use_rows)
{
    extern __shared__ __nv_bfloat16 smh[];
    __shared__ int rid[128];
    __shared__ float bsh[256];
    int bm = blockIdx.y * 128, bn = blockIdx.x * 256;
    if (mode == 2 && bm >= g_nrows) return;
    int t = threadIdx.x;
    if (t < 128) rid[t] = use_rows ? g_rows[bm + t] : (bm + t);
    if (mode == 2) bsh[t] = bias[bn + t];
    __syncthreads();
    mm256_body(smh, ((const __nv_bfloat16*)g_buf) + a_hoff, lda,
               ((const __nv_bfloat16*)g_buf) + w_hoff, ldw, bias,
               c_off, ldc, K, mode, bm, bn, rid, bsh);
}

// Fused Uh (x<2, mode0) + P (x>=2, mode1): grid (8, 16)
__global__ __launch_bounds__(256) void k_uhp(const float* __restrict__ U_b)
{
    extern __shared__ __nv_bfloat16 smh[];
    __shared__ int rid[128];
    int bm = blockIdx.y * 128;
    int t = threadIdx.x;
    if (t < 128) rid[t] = bm + t;
    __syncthreads();
    if (blockIdx.x < 2) {
        int bn = blockIdx.x * 256;
        mm256_body(smh, ((const __nv_bfloat16*)g_buf) + 2*OF_SRCHB, 1024,
                   ((const __nv_bfloat16*)g_buf) + 2*OF_UW16, 1024, U_b,
                   OF_UH, 512, 1024, 0, bm, bn, rid, (const float*)0);
    } else {
        int bn = (blockIdx.x - 2) * 256;
        mm256_body(smh, ((const __nv_bfloat16*)g_buf) + 2*OF_SRCHB, 1024,
                   ((const __nv_bfloat16*)g_buf) + 2*OF_WD16 + 512, 1536,
                   (const float*)0, OF_PB, 0, 1024, 1, bm, bn, rid,
                   (const float*)0);
    }
}

// Fused gate pre-GEMMs: seg 0=GXF 1=GXB 2=DGX. grid (18, 16)
__global__ __launch_bounds__(256) void k_gates256(
    const float* __restrict__ bf, const float* __restrict__ bb,
    const float* __restrict__ bd)
{
    extern __shared__ __nv_bfloat16 smh[];
    __shared__ int rid[128];
    int seg = blockIdx.x / 6, xb = blockIdx.x % 6;
    size_t a_hoff = (seg == 2) ? 2*OF_ETGTB : 2*OF_ESRCB;
    size_t w_hoff = (seg == 0) ? 2*OF_WF16 : (seg == 1) ? 2*OF_WB16 : 2*OF_WD16;
    int ldw = (seg == 2) ? 1536 : 512;
    const float* bias = (seg == 0) ? bf : (seg == 1) ? bb : bd;
    size_t c_off = (seg == 0) ? OF_GXF : (seg == 1) ? OF_GXB : OF_DGX;
    int bm = blockIdx.y * 128, bn = xb * 256;
    int t = threadIdx.x;
    if (t < 128) rid[t] = bm + t;
    __syncthreads();
    mm256_body(smh, ((const __nv_bfloat16*)g_buf) + a_hoff, 512,
               ((const __nv_bfloat16*)g_buf) + w_hoff, ldw, bias,
               c_off, 1536, 512, 0, bm, bn, rid, (const float*)0);
}

// ---------------------------------------------------------------------------
// Half-K gate dots: thread computes 3 dots of length 256 (its K half)
// against smem weights (stride 516) and smem h (stride 516).
// ---------------------------------------------------------------------------
__device__ __forceinline__ void gate_dots256(
    const float* __restrict__ wr_, const float* __restrict__ wz_,
    const float* __restrict__ wn_, const float* __restrict__ hr_,
    float& arO, float& azO, float& anO)
{
    float ar0=0.f, ar1=0.f, az0=0.f, az1=0.f, an0=0.f, an1=0.f;
#pragma unroll 2
    for (int kq = 0; kq < 16; kq++) {
        int kb = kq * 16;
        float4 h0 = *(const float4*)(hr_ + kb);
        float4 h1 = *(const float4*)(hr_ + kb + 4);
        float4 h2 = *(const float4*)(hr_ + kb + 8);
        float4 h3 = *(const float4*)(hr_ + kb + 12);
        float4 r0 = *(const float4*)(wr_ + kb);
        float4 r1 = *(const float4*)(wr_ + kb + 4);
        float4 r2 = *(const float4*)(wr_ + kb + 8);
        float4 r3 = *(const float4*)(wr_ + kb + 12);
        float4 z0 = *(const float4*)(wz_ + kb);
        float4 z1 = *(const float4*)(wz_ + kb + 4);
        float4 z2 = *(const float4*)(wz_ + kb + 8);
        float4 z3 = *(const float4*)(wz_ + kb + 12);
        float4 n0 = *(const float4*)(wn_ + kb);
        float4 n1 = *(const float4*)(wn_ + kb + 4);
        float4 n2 = *(const float4*)(wn_ + kb + 8);
        float4 n3 = *(const float4*)(wn_ + kb + 12);
        ar0 = dot4(h0, r0, ar0); ar1 = dot4(h1, r1, ar1);
        az0 = dot4(h0, z0, az0); az1 = dot4(h1, z1, az1);
        an0 = dot4(h0, n0, an0); an1 = dot4(h1, n1, an1);
        ar0 = dot4(h2, r2, ar0); ar1 = dot4(h3, r3, ar1);
        az0 = dot4(h2, z2, az0); az1 = dot4(h3, z3, az1);
        an0 = dot4(h2, n2, an0); an1 = dot4(h3, n3, an1);
    }
    arO = ar0 + ar1; azO = az0 + az1; anO = an0 + an1;
}

// ---------------------------------------------------------------------------
// Persistent encoder: 128 blocks x 512 thr (split-K=2), 64 steps, barrier 0.
// Whh slice (24x512) + full h (32x512) smem-resident. dyn smem 115584 B.
// ---------------------------------------------------------------------------
__global__ __launch_bounds__(512) void k_enc_all(
    const float* __restrict__ Whh_f, const float* __restrict__ bhh_f,
    const float* __restrict__ Whh_b, const float* __restrict__ bhh_b,
    const int* __restrict__ slen)
{
    extern __shared__ float dsm[];
    float* wsh = dsm;               // [24][516]
    float* Hsd = dsm + 24 * 516;    // [32][516]
    __shared__ float red[3][256];
    int bid = blockIdx.x;
    int dir = bid >> 6;
    int j0 = (bid & 63) * 8;
    const float* Whh = dir ? Whh_b : Whh_f;
    const float* bhh = dir ? bhh_b : bhh_f;
    size_t hb = dir ? OF_HB : OF_HF;
    const float* gx = g_buf + (dir ? OF_GXB : OF_GXF);
    __nv_bfloat16* srch = ((__nv_bfloat16*)g_buf) + 2*OF_SRCHB;
    int t = threadIdx.x;

    for (int i = t; i < 24 * 128; i += 512) {
        int wr = i >> 7, c4 = (i & 127) * 4;
        int gw = (wr >> 3) * 512 + j0 + (wr & 7);
        *(float4*)&wsh[wr * 516 + c4] = *(const float4*)(Whh + (size_t)gw * 512 + c4);
    }

    int kh = t >> 8;            // K half (0/1)
    int u  = t & 255;
    int rp = u >> 3, j = u & 7, jg = j0 + j;
    float br = bhh[jg], bz = bhh[512 + jg], bnn = bhh[1024 + jg];
    int sl = slen[rp];
    const float* wr_ = wsh + (size_t)j * 516 + kh * 256;
    const float* wz_ = wsh + (size_t)(8 + j) * 516 + kh * 256;
    const float* wn_ = wsh + (size_t)(16 + j) * 516 + kh * 256;
    const float* hr_ = Hsd + (size_t)rp * 516 + kh * 256;
    int hrr = t >> 4, hkv = t & 15;

    for (int s = 0; s < 64; s++) {
        if (s > 0) gridbar(0, (unsigned)(s - 1), 128);
        int pin = s & 1;
        const float* hin = g_buf + hb + (size_t)pin * 16384;
        float* hout = g_buf + hb + (size_t)(pin ^ 1) * 16384;
        int tt = dir ? (63 - s) : s;

        // stage full h (32x512): one float4 per thread
        *(float4*)&Hsd[hrr * 516 + hkv * 4] =
            *(const float4*)(hin + (size_t)hrr * 512 + hkv * 4);
        __syncthreads();

        float ar, az, an;
        gate_dots256(wr_, wz_, wn_, hr_, ar, az, an);
        if (kh == 1) { red[0][u] = ar; red[1][u] = az; red[2][u] = an; }
        __syncthreads();
        if (kh == 0) {
            ar += red[0][u]; az += red[1][u]; an += red[2][u];
            size_t grow = (size_t)rp * 64 + tt;
            float gxr = gx[grow*1536 + jg];
            float gxz = gx[grow*1536 + 512 + jg];
            float gxn = gx[grow*1536 + 1024 + jg];
            float rr = sigm(gxr + ar + br);
            float zz = sigm(gxz + az + bz);
            float nn = tanhf(gxn + rr * (an + bnn));
            float hold = hin[(size_t)rp*512 + jg];
            float hnew = (1.f - zz) * nn + zz * hold;
            bool m = tt < sl;
            hout[(size_t)rp*512 + jg] = m ? hnew : hold;
            srch[grow*1024 + (size_t)dir*512 + jg] = __float2bfloat16(m ? hnew : 0.f);
        }
    }
}

// ---------------------------------------------------------------------------
// Persistent decoder: 128 blocks x 512 thr, 64 steps.
//   blocks   0-31 : A — Uh[b] smem-resident; scores/softmax; publish alpha
//   blocks  32-63 : Q — qs = A_W-slice @ h (fp32 A_W smem-resident)
//   blocks 64-127 : G — split-K gate dots; split-S ctx from bf16 P^T; GRU
// barriers: idx1 = h ready (128), idx2 = qs ready (A+Q, 64), idx3 = alpha (128)
// dyn smem = 131072 B (A: Uh 64x512 f32; G: 24x516 W + 32x516 h)
// ---------------------------------------------------------------------------
__global__ __launch_bounds__(512) void k_dec_all(
    const float* __restrict__ A_W, const float* __restrict__ A_b,
    const float* __restrict__ A_v, const float* __restrict__ Whh,
    const float* __restrict__ bhh, const int* __restrict__ slen,
    const int* __restrict__ tlen)
{
    extern __shared__ float dsm[];
    __shared__ float es[64];
    __shared__ float als[32][64];
    __shared__ float red[3][256];

    int bid = blockIdx.x;
    int t = threadIdx.x;
    int lane = t & 31;
    bool isA = bid < 32;
    bool isQ = (bid >= 32 && bid < 64);
    bool isG = bid >= 64;
    int b   = bid;
    int qid = bid - 32;
    int j0  = (bid - 64) * 8;
    float* wsh = dsm;               // G: [24][516]
    float* Hsd = dsm + 24 * 516;    // G: [32][516]

    float avr[16], qb = 0.f;
    if (isA) {
        for (int i = t; i < 8192; i += 512)
            *(float4*)&dsm[(size_t)i*4] =
                *(const float4*)(g_buf + OF_UH + (size_t)b*32768 + (size_t)i*4);
#pragma unroll
        for (int k = 0; k < 16; k++) avr[k] = A_v[lane + 32*k];
    }
    if (isQ) {
        for (int i = t; i < 16 * 128; i += 512) {
            int r = i >> 7, c4 = (i & 127) * 4;
            *(float4*)&dsm[r * 516 + c4] =
                *(const float4*)(A_W + (size_t)(qid*16 + r) * 512 + c4);
        }
        qb = A_b[qid*16 + (t & 15)];
    }
    if (isG) {
        for (int i = t; i < 24 * 128; i += 512) {
            int wr = i >> 7, c4 = (i & 127) * 4;
            int gw = (wr >> 3) * 512 + j0 + (wr & 7);
            *(float4*)&wsh[wr * 516 + c4] =
                *(const float4*)(Whh + (size_t)gw * 512 + c4);
        }
    }
    __syncthreads();

    int kh = t >> 8;            // split half (0/1)
    int u  = t & 255;
    int rp = u >> 3, j = u & 7, jg = j0 + j;
    float br = 0.f, bz = 0.f, bnn = 0.f;
    int tl = 64;
    if (isG) {
        br = bhh[jg]; bz = bhh[512 + jg]; bnn = bhh[1024 + jg];
        tl = tlen[rp];
    }
    int sl = isA ? slen[b] : 0;
    const __nv_bfloat16* Pt = ((const __nv_bfloat16*)g_buf) + 2*OF_PB;
    __nv_bfloat16* dob = ((__nv_bfloat16*)g_buf) + 2*OF_DOB;
    const float* wr_ = wsh + (size_t)j * 516 + kh * 256;
    const float* wz_ = wsh + (size_t)(8 + j) * 516 + kh * 256;
    const float* wn_ = wsh + (size_t)(16 + j) * 516 + kh * 256;
    const float* hr_ = Hsd + (size_t)rp * 516 + kh * 256;
    int hrr = t >> 4, hkv = t & 15;

    for (int step = 0; step < 64; step++) {
        if (step > 0) gridbar(1, (unsigned)(step - 1), 128);   // h published
        int pin = step & 1;
        const float* hin = g_buf + OF_HD + (size_t)pin * 16384;
        float* hout = g_buf + OF_HD + (size_t)(pin ^ 1) * 16384;

        // ---- Q: qs = A_W @ h (one dot per thread) ----
        if (isQ) {
            int bb = t >> 4, jj = t & 15;
            const float* hrow = hin + (size_t)bb * 512;
            float acc = qb;
            for (int k = 0; k < 512; k += 4)
                acc = dot4(*(const float4*)&dsm[(size_t)jj*516 + k],
                           *(const float4*)(hrow + k), acc);
            g_buf[OF_QS + (size_t)bb * 512 + qid*16 + jj] = acc;
        }
        if (bid < 64) gridbar(2, (unsigned)step, 64);          // qs ready (A+Q)

        // ---- A: scores + softmax -> alpha (16 warps x 4 s each) ----
        if (isA) {
            float qr[16];
#pragma unroll
            for (int k = 0; k < 16; k++)
                qr[k] = g_buf[OF_QS + (size_t)b*512 + lane + 32*k];
            int w = t >> 5;
#pragma unroll
            for (int si = 0; si < 4; si++) {
                int s = w*4 + si;
                float acc = 0.f;
#pragma unroll
                for (int k = 0; k < 16; k++) {
                    float x = dsm[(size_t)s*512 + lane + 32*k] + qr[k];
                    float th;
                    asm("tanh.approx.f32 %0, %1;" : "=f"(th) : "f"(x));
                    acc = fmaf(avr[k], th, acc);
                }
#pragma unroll
                for (int o = 16; o > 0; o >>= 1)
                    acc += __shfl_xor_sync(0xffffffffu, acc, o);
                if (lane == 0) es[s] = (s < sl) ? acc : acc - 1e9f;
            }
            __syncthreads();
            if (t < 32) {
                float a0 = es[t], a1 = es[t + 32];
                float m = fmaxf(a0, a1);
#pragma unroll
                for (int o = 16; o > 0; o >>= 1)
                    m = fmaxf(m, __shfl_xor_sync(0xffffffffu, m, o));
                float e0 = __expf(a0 - m), e1 = __expf(a1 - m);
                float sum = e0 + e1;
#pragma unroll
                for (int o = 16; o > 0; o >>= 1)
                    sum += __shfl_xor_sync(0xffffffffu, sum, o);
                es[t] = e0 / sum; es[t + 32] = e1 / sum;
            }
            __syncthreads();
            if (t < 64) g_buf[OF_AL + (size_t)b*64 + t] = es[t];
        }

        // ---- G: split-K gate dots (overlaps Q/A; skips bar idx2) ----
        float ar = 0.f, az = 0.f, an = 0.f;
        if (isG) {
            *(float4*)&Hsd[hrr * 516 + hkv * 4] =
                *(const float4*)(hin + (size_t)hrr * 512 + hkv * 4);
            __syncthreads();
            gate_dots256(wr_, wz_, wn_, hr_, ar, az, an);
            if (kh == 1) { red[0][u] = ar; red[1][u] = az; red[2][u] = an; }
            __syncthreads();
            if (kh == 0) {
                ar += red[0][u]; az += red[1][u]; an += red[2][u];
            }
        }
        gridbar(3, (unsigned)step, 128);                       // alpha ready

        // ---- G: split-S ctx from bf16 P^T + pointwise GRU ----
        if (isG) {
            for (int i = t; i < 2048; i += 512)
                als[i >> 6][i & 63] = g_buf[OF_AL + i];
            __syncthreads();
            float cr = 0.f, cz = 0.f, cn = 0.f;
            const uint4* p0 = (const uint4*)(Pt + (size_t)rp*98304 + (size_t)jg*64) + kh*4;
            const uint4* p1 = (const uint4*)(Pt + (size_t)rp*98304 + (size_t)(512 + jg)*64) + kh*4;
            const uint4* p2 = (const uint4*)(Pt + (size_t)rp*98304 + (size_t)(1024 + jg)*64) + kh*4;
#pragma unroll
            for (int q = 0; q < 4; q++) {
                uint4 v0 = p0[q], v1 = p1[q], v2 = p2[q];
                const __nv_bfloat16* h0 = (const __nv_bfloat16*)&v0;
                const __nv_bfloat16* h1 = (const __nv_bfloat16*)&v1;
                const __nv_bfloat16* h2 = (const __nv_bfloat16*)&v2;
#pragma unroll
                for (int uu = 0; uu < 8; uu++) {
                    float al = als[rp][kh*32 + q*8 + uu];
                    cr = fmaf(al, __bfloat162float(h0[uu]), cr);
                    cz = fmaf(al, __bfloat162float(h1[uu]), cz);
                    cn = fmaf(al, __bfloat162float(h2[uu]), cn);
                }
            }
            if (kh == 1) { red[0][u] = cr; red[1][u] = cz; red[2][u] = cn; }
            __syncthreads();
            if (kh == 0) {
                cr += red[0][u]; cz += red[1][u]; cn += red[2][u];
                size_t grow = (size_t)rp*64 + step;
                const float* gx = g_buf + OF_DGX + grow*1536;
                float rr = sigm(gx[jg]        + cr + ar + br);
                float zz = sigm(gx[512 + jg]  + cz + az + bz);
                float nn = tanhf(gx[1024 + jg] + cn + rr * (an + bnn));
                float hold = hin[(size_t)rp*512 + jg];
                float hnew = (1.f - zz) * nn + zz * hold;
                bool m = step < tl;
                float o = m ? hnew : 0.f;
                hout[(size_t)rp*512 + jg] = m ? hnew : hold;
                g_buf[OF_DOUT + grow*512 + jg] = o;
                dob[grow*512 + jg] = __float2bfloat16(o);
            }
        }
    }
}

// ---------------------------------------------------------------------------
// Per-row: combine partials (live rows) or shared logZ0 (zero rows)
// ---------------------------------------------------------------------------
__global__ __launch_bounds__(256) void k_combine(
    const int* __restrict__ tgt, const float* __restrict__ out_w,
    const float* __restrict__ out_b, const int* __restrict__ tlen)
{
    int row = blockIdx.x * 8 + (threadIdx.x >> 5);
    int lane = threadIdx.x & 31;
    int b = row >> 6, tc = row & 63;
    int goal = (tc < 63) ? tgt[b*64 + tc + 1] : 0;
    float contrib = 0.f, cnt = 0.f;
    if (goal != 0) {
        bool live = tc < tlen[b];
        float M, L, d = 0.f;
        if (live) {
            const float* p = g_buf + OF_LP + (size_t)row * 256;
            M = -1e30f;
            for (int c = lane; c < 125; c += 32) M = fmaxf(M, p[c*2]);
#pragma unroll
            for (int o = 16; o > 0; o >>= 1)
                M = fmaxf(M, __shfl_xor_sync(0xffffffffu, M, o));
            L = 0.f;
            for (int c = lane; c < 125; c += 32) L += p[c*2+1] * __expf(p[c*2] - M);
#pragma unroll
            for (int o = 16; o > 0; o >>= 1)
                L += __shfl_xor_sync(0xffffffffu, L, o);
            const float* x = g_buf + OF_DOUT + (size_t)row * 512;
            const float* wrow = out_w + (size_t)goal * 512;
            for (int k = lane; k < 512; k += 32) d = fmaf(x[k], wrow[k], d);
#pragma unroll
            for (int o = 16; o > 0; o >>= 1)
                d += __shfl_xor_sync(0xffffffffu, d, o);
        } else {
            M = g_M0; L = g_L0;
        }
        contrib = (d + out_b[goal]) - (M + logf(L));
        cnt = 1.f;
    }
    if (lane == 0) {
        g_buf[OF_CON + row] = contrib;
        g_buf[OF_CNT + row] = cnt;
    }
}

// ---------------------------------------------------------------------------
// Final deterministic reduce -> loss
// ---------------------------------------------------------------------------
__global__ void k_final(float* out) {
    __shared__ float sc[1024], sn[1024];
    int t = threadIdx.x;
    sc[t] = g_buf[OF_CON + t] + g_buf[OF_CON + 1024 + t];
    sn[t] = g_buf[OF_CNT + t] + g_buf[OF_CNT + 1024 + t];
    __syncthreads();
    for (int o = 512; o > 0; o >>= 1) {
        if (t < o) { sc[t] += sc[t+o]; sn[t] += sn[t+o]; }
        __syncthreads();
    }
    if (t == 0) out[0] = -sc[0] / sn[0];
}

// ---------------------------------------------------------------------------
// Host orchestration (graph-capturable: kernel launches only, default stream)
// ---------------------------------------------------------------------------
extern "C" void kernel_launch(void* const* d_in, const int* in_sizes, int n_in,
                              void* d_out, int out_size)
{
    const int*   src_seqs = (const int*)  d_in[0];
    const int*   src_len  = (const int*)  d_in[1];
    const int*   tgt_seqs = (const int*)  d_in[2];
    const int*   tgt_len  = (const int*)  d_in[3];
    const float* src_emb  = (const float*)d_in[4];
    const float* eWih_f   = (const float*)d_in[5];
    const float* eWhh_f   = (const float*)d_in[6];
    const float* ebih_f   = (const float*)d_in[7];
    const float* ebhh_f   = (const float*)d_in[8];
    const float* eWih_b   = (const float*)d_in[9];
    const float* eWhh_b   = (const float*)d_in[10];
    const float* ebih_b   = (const float*)d_in[11];
    const float* ebhh_b   = (const float*)d_in[12];
    const float* tgt_emb  = (const float*)d_in[13];
    const float* dWih     = (const float*)d_in[14];
    const float* dWhh     = (const float*)d_in[15];
    const float* dbih     = (const float*)d_in[16];
    const float* dbhh     = (const float*)d_in[17];
    const float* U_w      = (const float*)d_in[18];
    const float* U_b      = (const float*)d_in[19];
    const float* A_W      = (const float*)d_in[20];
    const float* A_b      = (const float*)d_in[21];
    const float* A_v      = (const float*)d_in[22];
    const float* out_w    = (const float*)d_in[23];
    const float* out_b    = (const float*)d_in[24];

    cudaFuncSetAttribute(k_enc_all,  cudaFuncAttributeMaxDynamicSharedMemorySize, 115584);
    cudaFuncSetAttribute(k_dec_all,  cudaFuncAttributeMaxDynamicSharedMemorySize, 131072);
    cudaFuncSetAttribute(k_mm256,    cudaFuncAttributeMaxDynamicSharedMemorySize, 61440);
    cudaFuncSetAttribute(k_uhp,      cudaFuncAttributeMaxDynamicSharedMemorySize, 61440);
    cudaFuncSetAttribute(k_gates256, cudaFuncAttributeMaxDynamicSharedMemorySize, 61440);

    // 1: init (zero h, barrier state, row compaction, logZ0)
    k_init<<<66, 256>>>(tgt_len, out_b);
    // 2: all weight cvt + embeds in one launch
    k_prep<<<12224, 256>>>(eWih_f, eWih_b, dWih, U_w, out_w,
                           src_seqs, src_emb, tgt_seqs, tgt_emb);
    // 3: fused gate pre-GEMMs (GXF, GXB, DGX)
    k_gates256<<<dim3(18, 16), 256, 61440>>>(ebih_f, ebih_b, dbih);
    // 4: persistent bidirectional encoder (512 thr, split-K)
    k_enc_all<<<128, 512, 115584>>>(eWhh_f, ebhh_f, eWhh_b, ebhh_b, src_len);
    // 5: fused Uh + P
    k_uhp<<<dim3(8, 16), 256, 61440>>>(U_b);
    // 6: persistent decoder (512 thr; profiled by ncu -s 5 -c 1)
    k_dec_all<<<128, 512, 131072>>>(A_W, A_b, A_v, dWhh, dbhh, src_len, tgt_len);
    // 7: logits with fused log-softmax partials
    k_mm256<<<dim3(125, 16), 256, 61440>>>(2*OF_DOB, 512, 2*OF_OW16, 512,
                                           out_b, 0, 0, 512, 2, 1);
    // 8-9: combine + final reduce
    k_combine<<<256, 256>>>(tgt_seqs, out_w, out_b, tgt_len);
    k_final<<<1, 1024>>>((float*)d_out);
}